// round 8
// baseline (speedup 1.0000x reference)
#include <cuda_runtime.h>
#include <cuda_fp16.h>
#include <cstdint>

// ---------------------------------------------------------------------------
// B=8, L=2048, D=768.  fp16-in-gmem cp.async GEMMs, precision-tiered:
//   proj (fp32 in) : 3xFP16 register-staged; writes vp/lp as fp16 hi+lo
//   sim            : 3xFP16, all-fp16 cp.async
//   av/al          : 1xFP16, all-fp16 cp.async (transposed operands pre-built)
//   out            : 1xFP16 (comb fp16 x Wo16), cp.async
// ---------------------------------------------------------------------------
#define BATCH 8
#define SEQ   2048
#define DIM   768
#define TOK   (BATCH * SEQ)          // 16384

// Scratch (device globals: allocation-free rule)
__device__ __half g_vph [TOK * DIM];                 // vp hi   [16384,768]
__device__ __half g_vpl [TOK * DIM];                 // vp lo
__device__ __half g_lph [TOK * DIM];                 // lp hi
__device__ __half g_lpl [TOK * DIM];                 // lp lo
__device__ __half g_vpt [TOK * DIM];                 // vp^T   [8][768][2048]
__device__ __half g_lpt [TOK * DIM];                 // lp^T   [8][768][2048]
__device__ float  g_sim [(long)BATCH * SEQ * SEQ];   // [8,2048,2048]
__device__ __half g_at  [(long)BATCH * SEQ * SEQ];   // attn   [8][2048][2048]
__device__ __half g_att [(long)BATCH * SEQ * SEQ];   // attn^T [8][2048][2048]
__device__ __half g_cb  [(long)TOK * 2 * DIM];       // comb fp16 [16384,1536]
__device__ __half g_wo16[DIM * 2 * DIM];             // Wo fp16 [768,1536]

// ---------------------------------------------------------------------------
// helpers
// ---------------------------------------------------------------------------
__device__ __forceinline__ uint32_t smem_u32(const void* p) {
    uint32_t a;
    asm("{ .reg .u64 t; cvta.to.shared.u64 t, %1; cvt.u32.u64 %0, t; }"
        : "=r"(a) : "l"(p));
    return a;
}
__device__ __forceinline__ void cp16(uint32_t s, const void* g) {
    asm volatile("cp.async.ca.shared.global [%0], [%1], 16;" :: "r"(s), "l"(g));
}
#define CP_COMMIT() asm volatile("cp.async.commit_group;" ::: "memory")
template<int N>
__device__ __forceinline__ void cp_wait() {
    asm volatile("cp.async.wait_group %0;" :: "n"(N) : "memory");
}
__device__ __forceinline__ void mma16(float* d, const uint32_t* a, const uint32_t* b) {
    asm volatile(
        "mma.sync.aligned.m16n8k16.row.col.f32.f16.f16.f32 "
        "{%0,%1,%2,%3}, {%4,%5,%6,%7}, {%8,%9}, {%0,%1,%2,%3};"
        : "+f"(d[0]), "+f"(d[1]), "+f"(d[2]), "+f"(d[3])
        : "r"(a[0]), "r"(a[1]), "r"(a[2]), "r"(a[3]), "r"(b[0]), "r"(b[1]));
}
__device__ __forceinline__ uint32_t lds_u32(const __half* p) {
    return *reinterpret_cast<const uint32_t*>(p);
}
__device__ __forceinline__ void split_h(float a, __half& h, __half& l) {
    h = __float2half_rn(a);
    l = __float2half_rn(a - __half2float(h));
}

// SMEM tile: 128 rows x 32 k halves, row stride 40 halves (80 B)
#define ROWH    40
#define TILE16  (128 * ROWH)          // halves per tile (10240 B)

// ---------------------------------------------------------------------------
// fp16 cp.async stage loader: 128 rows x 32 k from src[(row0+r)*ld + k0 + c]
// ---------------------------------------------------------------------------
__device__ __forceinline__ void load_stage16(__half* dst, const __half* __restrict__ src,
                                             int ld, long row0, int k0, int tid)
{
#pragma unroll
    for (int p = 0; p < 2; ++p) {
        const int idx = tid + p * 256;       // 0..511
        const int r   = idx >> 2;            // 0..127
        const int c8  = (idx & 3) * 8;       // 0,8,16,24
        cp16(smem_u32(&dst[r * ROWH + c8]), &src[(row0 + r) * (long)ld + k0 + c8]);
    }
}

// ---------------------------------------------------------------------------
// All-fp16 GEMM body: mma.sync m16n8k16, CTA tile 128x128, K-chunk 32,
// NST-stage cp.async pipeline.  C[m,n] = sum_k opA[m,k]*opB[n,k]
//   SA/SB: operand has hi+lo tiles.  WMODE: 0 = fp32 out (+bias), 1 = fp16 out
// ---------------------------------------------------------------------------
template<bool SA, bool SB, int NST, int WMODE, bool BIAS>
__device__ __forceinline__ void gemm16_body(
    const __half* __restrict__ Ah, const __half* __restrict__ Al, int lda,
    const __half* __restrict__ Bh, const __half* __restrict__ Bl, int ldb,
    float* __restrict__ Cf, __half* __restrict__ Ch, int ldc,
    int K, const float* __restrict__ bias, __half* hsm)
{
    constexpr int NTIL = (SA ? 2 : 1) + (SB ? 2 : 1);
    constexpr int STG  = NTIL * TILE16;

    const int tid  = threadIdx.x;
    const int lane = tid & 31;
    const int wid  = tid >> 5;
    const int wm   = wid & 3;
    const int wn   = wid >> 2;
    const long m0  = (long)blockIdx.y * 128;
    const long n0  = (long)blockIdx.x * 128;
    const int lr   = lane >> 2;
    const int lc   = lane & 3;

    float acc[2][8][4];
#pragma unroll
    for (int i = 0; i < 2; ++i)
#pragma unroll
        for (int j = 0; j < 8; ++j)
#pragma unroll
            for (int q = 0; q < 4; ++q) acc[i][j][q] = 0.f;

    const int NIT = K / 32;

    auto issue = [&](int st) {
        if (st < NIT) {
            __half* s = hsm + (st % NST) * STG;
            const int k0 = st * 32;
            load_stage16(s, Ah, lda, m0, k0, tid);
            if (SA) load_stage16(s + TILE16, Al, lda, m0, k0, tid);
            __half* sb = s + (SA ? 2 : 1) * TILE16;
            load_stage16(sb, Bh, ldb, n0, k0, tid);
            if (SB) load_stage16(sb + TILE16, Bl, ldb, n0, k0, tid);
        }
        CP_COMMIT();
    };

#pragma unroll
    for (int s = 0; s < NST - 1; ++s) issue(s);

    for (int it = 0; it < NIT; ++it) {
        cp_wait<NST - 2>();
        __syncthreads();
        issue(it + NST - 1);

        const __half* At = hsm + (it % NST) * STG;
        const __half* AtL = At + TILE16;
        const __half* Bt = At + (SA ? 2 : 1) * TILE16;
        const __half* BtL = Bt + TILE16;

#pragma unroll
        for (int ks = 0; ks < 2; ++ks) {
            const int kb = ks * 16;
            uint32_t ah[2][4], al[2][4];
#pragma unroll
            for (int mt = 0; mt < 2; ++mt) {
                const int mb = wm * 32 + mt * 16;
                const int o0 = (mb + lr)     * ROWH + kb + 2 * lc;
                const int o1 = (mb + 8 + lr) * ROWH + kb + 2 * lc;
                ah[mt][0] = lds_u32(&At[o0]);
                ah[mt][1] = lds_u32(&At[o1]);
                ah[mt][2] = lds_u32(&At[o0 + 8]);
                ah[mt][3] = lds_u32(&At[o1 + 8]);
                if (SA) {
                    al[mt][0] = lds_u32(&AtL[o0]);
                    al[mt][1] = lds_u32(&AtL[o1]);
                    al[mt][2] = lds_u32(&AtL[o0 + 8]);
                    al[mt][3] = lds_u32(&AtL[o1 + 8]);
                }
            }
#pragma unroll
            for (int nt = 0; nt < 8; ++nt) {
                const int nb = wn * 64 + nt * 8;
                const int ob = (nb + lr) * ROWH + kb + 2 * lc;
                uint32_t bh[2], bl[2];
                bh[0] = lds_u32(&Bt[ob]);
                bh[1] = lds_u32(&Bt[ob + 8]);
                if (SB) {
                    bl[0] = lds_u32(&BtL[ob]);
                    bl[1] = lds_u32(&BtL[ob + 8]);
                }
#pragma unroll
                for (int mt = 0; mt < 2; ++mt) {
                    mma16(acc[mt][nt], ah[mt], bh);
                    if (SB) mma16(acc[mt][nt], ah[mt], bl);
                    if (SA) mma16(acc[mt][nt], al[mt], bh);
                }
            }
        }
    }

    // ---- epilogue ----
#pragma unroll
    for (int mt = 0; mt < 2; ++mt) {
        const long r0 = m0 + wm * 32 + mt * 16 + lr;
#pragma unroll
        for (int nt = 0; nt < 8; ++nt) {
            const long c = n0 + wn * 64 + nt * 8 + lc * 2;
            float v[4] = {acc[mt][nt][0], acc[mt][nt][1], acc[mt][nt][2], acc[mt][nt][3]};
            if (BIAS) {
                float2 bb = *reinterpret_cast<const float2*>(&bias[c]);
                v[0] += bb.x; v[1] += bb.y; v[2] += bb.x; v[3] += bb.y;
            }
            if (WMODE == 1) {
                *reinterpret_cast<__half2*>(&Ch[r0 * ldc + c])       = __floats2half2_rn(v[0], v[1]);
                *reinterpret_cast<__half2*>(&Ch[(r0 + 8) * ldc + c]) = __floats2half2_rn(v[2], v[3]);
            } else {
                *reinterpret_cast<float2*>(&Cf[r0 * ldc + c])       = make_float2(v[0], v[1]);
                *reinterpret_cast<float2*>(&Cf[(r0 + 8) * ldc + c]) = make_float2(v[2], v[3]);
            }
        }
    }
}

// ---------------------------------------------------------------------------
// Projection kernel (fp32 inputs): 3x register-staged, writes fp16 hi/lo.
// ---------------------------------------------------------------------------
#define PROWH    40
#define PTILE_H  (128 * PROWH)
#define PSTAGE_H (4 * PTILE_H)
#define PSMEM_B  (3 * PSTAGE_H * 2)   // 122880

__device__ __forceinline__ void p_ldg(const float* __restrict__ G, int ld,
                                      long row0, int k0, int tid, float* v)
{
#pragma unroll
    for (int p = 0; p < 4; ++p) {
        const int idx = tid + p * 256;
        const int r   = idx >> 3;
        const int c4  = (idx & 7) * 4;
        float4 t = *reinterpret_cast<const float4*>(&G[(row0 + r) * (long)ld + k0 + c4]);
        v[p * 4 + 0] = t.x; v[p * 4 + 1] = t.y;
        v[p * 4 + 2] = t.z; v[p * 4 + 3] = t.w;
    }
}
__device__ __forceinline__ void p_sts(const float* v, __half* Shi, __half* Slo, int tid)
{
#pragma unroll
    for (int p = 0; p < 4; ++p) {
        __half h[4], l[4];
#pragma unroll
        for (int j = 0; j < 4; ++j) split_h(v[p * 4 + j], h[j], l[j]);
        const int idx = tid + p * 256;
        const int r = idx >> 3, c = (idx & 7) * 4;
        *reinterpret_cast<__half2*>(&Shi[r * PROWH + c])     = __halves2half2(h[0], h[1]);
        *reinterpret_cast<__half2*>(&Shi[r * PROWH + c + 2]) = __halves2half2(h[2], h[3]);
        *reinterpret_cast<__half2*>(&Slo[r * PROWH + c])     = __halves2half2(l[0], l[1]);
        *reinterpret_cast<__half2*>(&Slo[r * PROWH + c + 2]) = __halves2half2(l[2], l[3]);
    }
}

__global__ __launch_bounds__(256)
void proj_both(const float* __restrict__ Vf, const float* __restrict__ Lf,
               const float* __restrict__ Wv, const float* __restrict__ bv,
               const float* __restrict__ Wl, const float* __restrict__ bl,
               __half* __restrict__ vph, __half* __restrict__ vpl,
               __half* __restrict__ lph, __half* __restrict__ lpl)
{
    extern __shared__ __half hsm[];
    const int z = blockIdx.z;
    const float* A    = z ? Lf : Vf;
    const float* B    = z ? Wl : Wv;
    const float* bias = z ? bl : bv;
    __half* Ch = z ? lph : vph;
    __half* Cl = z ? lpl : vpl;

    const int tid  = threadIdx.x;
    const int lane = tid & 31;
    const int wid  = tid >> 5;
    const int wm   = wid & 3;
    const int wn   = wid >> 2;
    const long m0  = (long)blockIdx.y * 128;
    const long n0  = (long)blockIdx.x * 128;
    const int lr   = lane >> 2;
    const int lc   = lane & 3;

    float acc[2][8][4];
#pragma unroll
    for (int i = 0; i < 2; ++i)
#pragma unroll
        for (int j = 0; j < 8; ++j)
#pragma unroll
            for (int q = 0; q < 4; ++q) acc[i][j][q] = 0.f;

    const int NIT = DIM / 32;   // 24
    float ra[16], rb[16];

    p_ldg(A, DIM, m0, 0, tid, ra);
    p_ldg(B, DIM, n0, 0, tid, rb);
    p_sts(ra, hsm,               hsm + PTILE_H,     tid);
    p_sts(rb, hsm + 2 * PTILE_H, hsm + 3 * PTILE_H, tid);
    p_ldg(A, DIM, m0, 32, tid, ra);
    p_ldg(B, DIM, n0, 32, tid, rb);

    for (int it = 0; it < NIT; ++it) {
        __syncthreads();
        if (it + 1 < NIT) {
            __half* st = hsm + ((it + 1) % 3) * PSTAGE_H;
            p_sts(ra, st,               st + PTILE_H,     tid);
            p_sts(rb, st + 2 * PTILE_H, st + 3 * PTILE_H, tid);
        }
        if (it + 2 < NIT) {
            p_ldg(A, DIM, m0, (it + 2) * 32, tid, ra);
            p_ldg(B, DIM, n0, (it + 2) * 32, tid, rb);
        }
        const __half* Ahi = hsm + (it % 3) * PSTAGE_H;
        const __half* Alo = Ahi + PTILE_H;
        const __half* Bhi = Ahi + 2 * PTILE_H;
        const __half* Blo = Ahi + 3 * PTILE_H;

#pragma unroll
        for (int ks = 0; ks < 2; ++ks) {
            const int kb = ks * 16;
            uint32_t ah[2][4], al[2][4];
#pragma unroll
            for (int mt = 0; mt < 2; ++mt) {
                const int mb = wm * 32 + mt * 16;
                const int o0 = (mb + lr)     * PROWH + kb + 2 * lc;
                const int o1 = (mb + 8 + lr) * PROWH + kb + 2 * lc;
                ah[mt][0] = lds_u32(&Ahi[o0]);
                ah[mt][1] = lds_u32(&Ahi[o1]);
                ah[mt][2] = lds_u32(&Ahi[o0 + 8]);
                ah[mt][3] = lds_u32(&Ahi[o1 + 8]);
                al[mt][0] = lds_u32(&Alo[o0]);
                al[mt][1] = lds_u32(&Alo[o1]);
                al[mt][2] = lds_u32(&Alo[o0 + 8]);
                al[mt][3] = lds_u32(&Alo[o1 + 8]);
            }
#pragma unroll
            for (int nt = 0; nt < 8; ++nt) {
                const int nb = wn * 64 + nt * 8;
                const int ob = (nb + lr) * PROWH + kb + 2 * lc;
                uint32_t bh[2], bl[2];
                bh[0] = lds_u32(&Bhi[ob]);
                bh[1] = lds_u32(&Bhi[ob + 8]);
                bl[0] = lds_u32(&Blo[ob]);
                bl[1] = lds_u32(&Blo[ob + 8]);
#pragma unroll
                for (int mt = 0; mt < 2; ++mt) {
                    mma16(acc[mt][nt], ah[mt], bh);
                    mma16(acc[mt][nt], ah[mt], bl);
                    mma16(acc[mt][nt], al[mt], bh);
                }
            }
        }
    }

    // epilogue: +bias, split to hi/lo fp16
#pragma unroll
    for (int mt = 0; mt < 2; ++mt) {
        const long r0 = m0 + wm * 32 + mt * 16 + lr;
#pragma unroll
        for (int nt = 0; nt < 8; ++nt) {
            const long c = n0 + wn * 64 + nt * 8 + lc * 2;
            float2 bb = *reinterpret_cast<const float2*>(&bias[c]);
            float v[4] = {acc[mt][nt][0] + bb.x, acc[mt][nt][1] + bb.y,
                          acc[mt][nt][2] + bb.x, acc[mt][nt][3] + bb.y};
            __half h[4], l[4];
#pragma unroll
            for (int q = 0; q < 4; ++q) split_h(v[q], h[q], l[q]);
            *reinterpret_cast<__half2*>(&Ch[r0 * DIM + c])       = __halves2half2(h[0], h[1]);
            *reinterpret_cast<__half2*>(&Ch[(r0 + 8) * DIM + c]) = __halves2half2(h[2], h[3]);
            *reinterpret_cast<__half2*>(&Cl[r0 * DIM + c])       = __halves2half2(l[0], l[1]);
            *reinterpret_cast<__half2*>(&Cl[(r0 + 8) * DIM + c]) = __halves2half2(l[2], l[3]);
        }
    }
}

// ---------------------------------------------------------------------------
// GEMM kernel wrappers
// ---------------------------------------------------------------------------
// sim[b] = (vph+vpl)(lph+lpl)^T, 3x, fp32 out.  grid (16,16,8), smem 122880
__global__ __launch_bounds__(256)
void sim_gemm(const __half* __restrict__ vph, const __half* __restrict__ vpl,
              const __half* __restrict__ lph, const __half* __restrict__ lpl,
              float* __restrict__ sim)
{
    extern __shared__ __half hsm[];
    const long b  = blockIdx.z;
    const long sF = (long)SEQ * DIM;
    const long sS = (long)SEQ * SEQ;
    gemm16_body<true, true, 3, 0, false>(
        vph + b * sF, vpl + b * sF, DIM,
        lph + b * sF, lpl + b * sF, DIM,
        sim + b * sS, nullptr, SEQ, DIM, nullptr, hsm);
}

// av/al, 1x, writes comb fp16.  grid (6,16,16), smem 81920, 2 CTAs/SM
__global__ __launch_bounds__(256, 2)
void avl_gemm(const __half* __restrict__ at,  const __half* __restrict__ att,
              const __half* __restrict__ vpt, const __half* __restrict__ lpt,
              __half* __restrict__ cb)
{
    extern __shared__ __half hsm[];
    const int z   = blockIdx.z;
    const long b  = z & 7;
    const long sS = (long)SEQ * SEQ;
    const long sF = (long)SEQ * DIM;
    const long sO = (long)SEQ * 2 * DIM;
    const __half* A = (z >> 3) ? (att + b * sS) : (at + b * sS);
    const __half* B = (z >> 3) ? (lpt + b * sF) : (vpt + b * sF);
    const long    co = b * sO + ((z >> 3) ? DIM : 0);
    gemm16_body<false, false, 4, 1, false>(
        A, nullptr, SEQ, B, nullptr, SEQ,
        nullptr, cb + co, 2 * DIM, SEQ, nullptr, hsm);
}

// out = cb @ Wo16^T + bo, 1x, fp32 out.  grid (6,128,1), smem 61440, 2 CTAs/SM
__global__ __launch_bounds__(256, 2)
void out_gemm(const __half* __restrict__ cb,
              const __half* __restrict__ wo, const float* __restrict__ bo,
              float* __restrict__ out)
{
    extern __shared__ __half hsm[];
    gemm16_body<false, false, 3, 0, true>(
        cb, nullptr, 2 * DIM, wo, nullptr, 2 * DIM,
        out, nullptr, DIM, 2 * DIM, bo, hsm);
}

// ---------------------------------------------------------------------------
// fp16 transpose, 64x64 tiles, uint4 I/O, XOR-swizzled smem (<=2-way LDS).
//   dst[b][x][y] = src[b][y][x].  src [R][C], dst [C][R].
// block 256, grid (C/64, R/64, BATCHES)
// ---------------------------------------------------------------------------
__global__ __launch_bounds__(256)
void transpose64(const __half* __restrict__ src, __half* __restrict__ dst,
                 int R, int C, long stride)
{
    __shared__ uint4 t[64 * 8];
    const long b  = blockIdx.z;
    const int  x0 = blockIdx.x * 64;
    const int  y0 = blockIdx.y * 64;
    const __half* s = src + b * stride;
    __half*       d = dst + b * stride;
    const int tid  = threadIdx.x;
    const int lane = tid & 31;

#pragma unroll
    for (int p = 0; p < 2; ++p) {
        const int u = tid + p * 256;      // 0..511
        const int r = u >> 3;             // 0..63
        const int c = u & 7;              // 0..7
        uint4 v = *reinterpret_cast<const uint4*>(&s[(long)(y0 + r) * C + x0 + c * 8]);
        t[r * 8 + (c ^ (r & 7))] = v;
    }
    __syncthreads();

    const __half* th = reinterpret_cast<const __half*>(t);
#pragma unroll
    for (int p = 0; p < 2; ++p) {
        const int u  = tid + p * 256;
        const int xr = u >> 3;            // dst row = src col, 0..63
        const int cy = (u & 7) * 8;       // dst col base = src row, 0..56
        __half v[8];
#pragma unroll
        for (int sph = 0; sph < 8; ++sph) {
            const int q = ((lane & 7) + sph) & 7;   // stagger phases across lanes
            const int y = cy + q;                   // y & 7 == q
            v[q] = th[((y * 8) + ((xr >> 3) ^ q)) * 8 + (xr & 7)];
        }
        uint4 o;
        __half* ov = reinterpret_cast<__half*>(&o);
#pragma unroll
        for (int q = 0; q < 8; ++q) ov[q] = v[q];
        *reinterpret_cast<uint4*>(&d[(long)(x0 + xr) * R + y0 + cy]) = o;
    }
}

// Wo fp32 -> fp16
__global__ __launch_bounds__(256)
void wo_convert(const float* __restrict__ Wo, __half* __restrict__ wo16)
{
    const int i = blockIdx.x * 256 + threadIdx.x;
    float2 v = *reinterpret_cast<const float2*>(&Wo[i * 2]);
    *reinterpret_cast<__half2*>(&wo16[i * 2]) = __floats2half2_rn(v.x, v.y);
}

// ---------------------------------------------------------------------------
// Row softmax: sim fp32 -> attn fp16. One block per row of 2048.
// ---------------------------------------------------------------------------
__global__ __launch_bounds__(256)
void softmax2048h(const float* __restrict__ S, __half* __restrict__ O)
{
    const float* p = S + (long)blockIdx.x * 2048;
    __half*      o = O + (long)blockIdx.x * 2048;
    const int tid = threadIdx.x;

    float4 v0 = reinterpret_cast<const float4*>(p)[tid];
    float4 v1 = reinterpret_cast<const float4*>(p)[tid + 256];

    float mx = fmaxf(fmaxf(fmaxf(v0.x, v0.y), fmaxf(v0.z, v0.w)),
                     fmaxf(fmaxf(v1.x, v1.y), fmaxf(v1.z, v1.w)));

    __shared__ float red[8];
#pragma unroll
    for (int ofs = 16; ofs > 0; ofs >>= 1) mx = fmaxf(mx, __shfl_xor_sync(0xffffffffu, mx, ofs));
    if ((tid & 31) == 0) red[tid >> 5] = mx;
    __syncthreads();
    if (tid == 0) {
        float m = red[0];
#pragma unroll
        for (int w = 1; w < 8; ++w) m = fmaxf(m, red[w]);
        red[0] = m;
    }
    __syncthreads();
    mx = red[0];
    __syncthreads();

    v0.x = __expf(v0.x - mx); v0.y = __expf(v0.y - mx);
    v0.z = __expf(v0.z - mx); v0.w = __expf(v0.w - mx);
    v1.x = __expf(v1.x - mx); v1.y = __expf(v1.y - mx);
    v1.z = __expf(v1.z - mx); v1.w = __expf(v1.w - mx);

    float s = (v0.x + v0.y + v0.z + v0.w) + (v1.x + v1.y + v1.z + v1.w);
#pragma unroll
    for (int ofs = 16; ofs > 0; ofs >>= 1) s += __shfl_xor_sync(0xffffffffu, s, ofs);
    if ((tid & 31) == 0) red[tid >> 5] = s;
    __syncthreads();
    if (tid == 0) {
        float t = 0.f;
#pragma unroll
        for (int w = 0; w < 8; ++w) t += red[w];
        red[0] = t;
    }
    __syncthreads();
    const float inv = 1.0f / red[0];

    uint2 o0, o1;
    *reinterpret_cast<__half2*>(&o0.x) = __floats2half2_rn(v0.x * inv, v0.y * inv);
    *reinterpret_cast<__half2*>(&o0.y) = __floats2half2_rn(v0.z * inv, v0.w * inv);
    *reinterpret_cast<__half2*>(&o1.x) = __floats2half2_rn(v1.x * inv, v1.y * inv);
    *reinterpret_cast<__half2*>(&o1.y) = __floats2half2_rn(v1.z * inv, v1.w * inv);
    reinterpret_cast<uint2*>(o)[tid]       = o0;
    reinterpret_cast<uint2*>(o)[tid + 256] = o1;
}

// ---------------------------------------------------------------------------
// Launch
// ---------------------------------------------------------------------------
extern "C" void kernel_launch(void* const* d_in, const int* in_sizes, int n_in,
                              void* d_out, int out_size)
{
    const float* Vf = (const float*)d_in[0];
    const float* Lf = (const float*)d_in[1];
    const float* Wv = (const float*)d_in[2];
    const float* bv = (const float*)d_in[3];
    const float* Wl = (const float*)d_in[4];
    const float* bl = (const float*)d_in[5];
    const float* Wo = (const float*)d_in[6];
    const float* bo = (const float*)d_in[7];
    float* out = (float*)d_out;

    __half *vph, *vpl, *lph, *lpl, *vpt, *lpt, *at, *att, *cb, *wo16;
    float* sim;
    cudaGetSymbolAddress((void**)&vph, g_vph);
    cudaGetSymbolAddress((void**)&vpl, g_vpl);
    cudaGetSymbolAddress((void**)&lph, g_lph);
    cudaGetSymbolAddress((void**)&lpl, g_lpl);
    cudaGetSymbolAddress((void**)&vpt, g_vpt);
    cudaGetSymbolAddress((void**)&lpt, g_lpt);
    cudaGetSymbolAddress((void**)&sim, g_sim);
    cudaGetSymbolAddress((void**)&at,  g_at);
    cudaGetSymbolAddress((void**)&att, g_att);
    cudaGetSymbolAddress((void**)&cb,  g_cb);
    cudaGetSymbolAddress((void**)&wo16, g_wo16);

    cudaFuncSetAttribute(proj_both, cudaFuncAttributeMaxDynamicSharedMemorySize, PSMEM_B);
    cudaFuncSetAttribute(sim_gemm,  cudaFuncAttributeMaxDynamicSharedMemorySize, 4 * TILE16 * 3 * 2);
    cudaFuncSetAttribute(avl_gemm,  cudaFuncAttributeMaxDynamicSharedMemorySize, 2 * TILE16 * 4 * 2);
    cudaFuncSetAttribute(out_gemm,  cudaFuncAttributeMaxDynamicSharedMemorySize, 2 * TILE16 * 3 * 2);

    const dim3 blk(256);
    const long sF = (long)SEQ * DIM;
    const long sS = (long)SEQ * SEQ;

    // Wo fp16 (independent)
    wo_convert<<<DIM * 2 * DIM / 512, blk>>>(Wo, wo16);
    // projections -> vp/lp hi+lo fp16
    proj_both<<<dim3(DIM/128, TOK/128, 2), blk, PSMEM_B>>>(
        Vf, Lf, Wv, bv, Wl, bl, vph, vpl, lph, lpl);
    // transposed fp16 copies for av/al
    transpose64<<<dim3(DIM/64, SEQ/64, BATCH), blk>>>(vph, vpt, SEQ, DIM, sF);
    transpose64<<<dim3(DIM/64, SEQ/64, BATCH), blk>>>(lph, lpt, SEQ, DIM, sF);
    // sim (3x)
    sim_gemm<<<dim3(SEQ/128, SEQ/128, BATCH), blk, 4 * TILE16 * 3 * 2>>>(
        vph, vpl, lph, lpl, sim);
    // softmax -> attn fp16
    softmax2048h<<<TOK, blk>>>(sim, at);
    // attn^T fp16
    transpose64<<<dim3(SEQ/64, SEQ/64, BATCH), blk>>>(at, att, SEQ, SEQ, sS);
    // av + al (1x) -> comb fp16
    avl_gemm<<<dim3(DIM/128, SEQ/128, 2 * BATCH), blk, 2 * TILE16 * 4 * 2>>>(
        at, att, vpt, lpt, cb);
    // out (1x)
    out_gemm<<<dim3(DIM/128, TOK/128, 1), blk, 2 * TILE16 * 3 * 2>>>(
        cb, wo16, bo, out);
}

// round 9
// speedup vs baseline: 1.1044x; 1.1044x over previous
#include <cuda_runtime.h>
#include <cuda_fp16.h>
#include <cstdint>

// ---------------------------------------------------------------------------
// B=8, L=2048, D=768.  fp16-in-gmem cp.async GEMMs, precision-tiered:
//   proj (fp32 in) : 3xFP16 register-staged; writes vp/lp as fp16 hi+lo
//   sim            : 3xFP16, all-fp16 cp.async
//   av/al          : 1xFP16, all-fp16 cp.async (transposed operands pre-built)
//   out            : 1xFP16 (comb fp16 x Wo16), cp.async
// ---------------------------------------------------------------------------
#define BATCH 8
#define SEQ   2048
#define DIM   768
#define TOK   (BATCH * SEQ)          // 16384

// Scratch (device globals: allocation-free rule)
__device__ __half g_vph [TOK * DIM];                 // vp hi   [16384,768]
__device__ __half g_vpl [TOK * DIM];                 // vp lo
__device__ __half g_lph [TOK * DIM];                 // lp hi
__device__ __half g_lpl [TOK * DIM];                 // lp lo
__device__ __half g_vpt [TOK * DIM];                 // vp^T   [8][768][2048]
__device__ __half g_lpt [TOK * DIM];                 // lp^T   [8][768][2048]
__device__ float  g_sim [(long)BATCH * SEQ * SEQ];   // [8,2048,2048]
__device__ __half g_at  [(long)BATCH * SEQ * SEQ];   // attn   [8][2048][2048]
__device__ __half g_att [(long)BATCH * SEQ * SEQ];   // attn^T [8][2048][2048]
__device__ __half g_cb  [(long)TOK * 2 * DIM];       // comb fp16 [16384,1536]
__device__ __half g_wo16[DIM * 2 * DIM];             // Wo fp16 [768,1536]

// ---------------------------------------------------------------------------
// helpers
// ---------------------------------------------------------------------------
__device__ __forceinline__ uint32_t smem_u32(const void* p) {
    uint32_t a;
    asm("{ .reg .u64 t; cvta.to.shared.u64 t, %1; cvt.u32.u64 %0, t; }"
        : "=r"(a) : "l"(p));
    return a;
}
__device__ __forceinline__ void cp16(uint32_t s, const void* g) {
    asm volatile("cp.async.ca.shared.global [%0], [%1], 16;" :: "r"(s), "l"(g));
}
#define CP_COMMIT() asm volatile("cp.async.commit_group;" ::: "memory")
template<int N>
__device__ __forceinline__ void cp_wait() {
    asm volatile("cp.async.wait_group %0;" :: "n"(N) : "memory");
}
__device__ __forceinline__ void mma16(float* d, const uint32_t* a, const uint32_t* b) {
    asm volatile(
        "mma.sync.aligned.m16n8k16.row.col.f32.f16.f16.f32 "
        "{%0,%1,%2,%3}, {%4,%5,%6,%7}, {%8,%9}, {%0,%1,%2,%3};"
        : "+f"(d[0]), "+f"(d[1]), "+f"(d[2]), "+f"(d[3])
        : "r"(a[0]), "r"(a[1]), "r"(a[2]), "r"(a[3]), "r"(b[0]), "r"(b[1]));
}
__device__ __forceinline__ uint32_t lds_u32(const __half* p) {
    return *reinterpret_cast<const uint32_t*>(p);
}
__device__ __forceinline__ void split_h(float a, __half& h, __half& l) {
    h = __float2half_rn(a);
    l = __float2half_rn(a - __half2float(h));
}

// SMEM tile: 128 rows x 32 k halves, row stride 40 halves (80 B)
#define ROWH    40
#define TILE16  (128 * ROWH)          // halves per tile (10240 B)

// ---------------------------------------------------------------------------
// fp16 cp.async stage loader: 128 rows x 32 k from src[(row0+r)*ld + k0 + c]
// ---------------------------------------------------------------------------
__device__ __forceinline__ void load_stage16(__half* dst, const __half* __restrict__ src,
                                             int ld, long row0, int k0, int tid)
{
#pragma unroll
    for (int p = 0; p < 2; ++p) {
        const int idx = tid + p * 256;       // 0..511
        const int r   = idx >> 2;            // 0..127
        const int c8  = (idx & 3) * 8;       // 0,8,16,24
        cp16(smem_u32(&dst[r * ROWH + c8]), &src[(row0 + r) * (long)ld + k0 + c8]);
    }
}

// ---------------------------------------------------------------------------
// All-fp16 GEMM body: mma.sync m16n8k16, CTA tile 128x128, K-chunk 32,
// NST-stage cp.async pipeline.  C[m,n] = sum_k opA[m,k]*opB[n,k]
//   SA/SB: operand has hi+lo tiles.  WMODE: 0 = fp32 out (+bias), 1 = fp16 out
// ---------------------------------------------------------------------------
template<bool SA, bool SB, int NST, int WMODE, bool BIAS>
__device__ __forceinline__ void gemm16_body(
    const __half* __restrict__ Ah, const __half* __restrict__ Al, int lda,
    const __half* __restrict__ Bh, const __half* __restrict__ Bl, int ldb,
    float* __restrict__ Cf, __half* __restrict__ Ch, int ldc,
    int K, const float* __restrict__ bias, __half* hsm)
{
    constexpr int NTIL = (SA ? 2 : 1) + (SB ? 2 : 1);
    constexpr int STG  = NTIL * TILE16;

    const int tid  = threadIdx.x;
    const int lane = tid & 31;
    const int wid  = tid >> 5;
    const int wm   = wid & 3;
    const int wn   = wid >> 2;
    const long m0  = (long)blockIdx.y * 128;
    const long n0  = (long)blockIdx.x * 128;
    const int lr   = lane >> 2;
    const int lc   = lane & 3;

    float acc[2][8][4];
#pragma unroll
    for (int i = 0; i < 2; ++i)
#pragma unroll
        for (int j = 0; j < 8; ++j)
#pragma unroll
            for (int q = 0; q < 4; ++q) acc[i][j][q] = 0.f;

    const int NIT = K / 32;

    auto issue = [&](int st) {
        if (st < NIT) {
            __half* s = hsm + (st % NST) * STG;
            const int k0 = st * 32;
            load_stage16(s, Ah, lda, m0, k0, tid);
            if (SA) load_stage16(s + TILE16, Al, lda, m0, k0, tid);
            __half* sb = s + (SA ? 2 : 1) * TILE16;
            load_stage16(sb, Bh, ldb, n0, k0, tid);
            if (SB) load_stage16(sb + TILE16, Bl, ldb, n0, k0, tid);
        }
        CP_COMMIT();
    };

#pragma unroll
    for (int s = 0; s < NST - 1; ++s) issue(s);

    for (int it = 0; it < NIT; ++it) {
        cp_wait<NST - 2>();
        __syncthreads();
        issue(it + NST - 1);

        const __half* At = hsm + (it % NST) * STG;
        const __half* AtL = At + TILE16;
        const __half* Bt = At + (SA ? 2 : 1) * TILE16;
        const __half* BtL = Bt + TILE16;

#pragma unroll
        for (int ks = 0; ks < 2; ++ks) {
            const int kb = ks * 16;
            uint32_t ah[2][4], al[2][4];
#pragma unroll
            for (int mt = 0; mt < 2; ++mt) {
                const int mb = wm * 32 + mt * 16;
                const int o0 = (mb + lr)     * ROWH + kb + 2 * lc;
                const int o1 = (mb + 8 + lr) * ROWH + kb + 2 * lc;
                ah[mt][0] = lds_u32(&At[o0]);
                ah[mt][1] = lds_u32(&At[o1]);
                ah[mt][2] = lds_u32(&At[o0 + 8]);
                ah[mt][3] = lds_u32(&At[o1 + 8]);
                if (SA) {
                    al[mt][0] = lds_u32(&AtL[o0]);
                    al[mt][1] = lds_u32(&AtL[o1]);
                    al[mt][2] = lds_u32(&AtL[o0 + 8]);
                    al[mt][3] = lds_u32(&AtL[o1 + 8]);
                }
            }
#pragma unroll
            for (int nt = 0; nt < 8; ++nt) {
                const int nb = wn * 64 + nt * 8;
                const int ob = (nb + lr) * ROWH + kb + 2 * lc;
                uint32_t bh[2], bl[2];
                bh[0] = lds_u32(&Bt[ob]);
                bh[1] = lds_u32(&Bt[ob + 8]);
                if (SB) {
                    bl[0] = lds_u32(&BtL[ob]);
                    bl[1] = lds_u32(&BtL[ob + 8]);
                }
#pragma unroll
                for (int mt = 0; mt < 2; ++mt) {
                    mma16(acc[mt][nt], ah[mt], bh);
                    if (SB) mma16(acc[mt][nt], ah[mt], bl);
                    if (SA) mma16(acc[mt][nt], al[mt], bh);
                }
            }
        }
    }

    // ---- epilogue ----
#pragma unroll
    for (int mt = 0; mt < 2; ++mt) {
        const long r0 = m0 + wm * 32 + mt * 16 + lr;
#pragma unroll
        for (int nt = 0; nt < 8; ++nt) {
            const long c = n0 + wn * 64 + nt * 8 + lc * 2;
            float v[4] = {acc[mt][nt][0], acc[mt][nt][1], acc[mt][nt][2], acc[mt][nt][3]};
            if (BIAS) {
                float2 bb = *reinterpret_cast<const float2*>(&bias[c]);
                v[0] += bb.x; v[1] += bb.y; v[2] += bb.x; v[3] += bb.y;
            }
            if (WMODE == 1) {
                *reinterpret_cast<__half2*>(&Ch[r0 * ldc + c])       = __floats2half2_rn(v[0], v[1]);
                *reinterpret_cast<__half2*>(&Ch[(r0 + 8) * ldc + c]) = __floats2half2_rn(v[2], v[3]);
            } else {
                *reinterpret_cast<float2*>(&Cf[r0 * ldc + c])       = make_float2(v[0], v[1]);
                *reinterpret_cast<float2*>(&Cf[(r0 + 8) * ldc + c]) = make_float2(v[2], v[3]);
            }
        }
    }
}

// ---------------------------------------------------------------------------
// Projection kernel (fp32 inputs): 3x register-staged, writes fp16 hi/lo.
// ---------------------------------------------------------------------------
#define PROWH    40
#define PTILE_H  (128 * PROWH)
#define PSTAGE_H (4 * PTILE_H)
#define PSMEM_B  (3 * PSTAGE_H * 2)   // 122880

__device__ __forceinline__ void p_ldg(const float* __restrict__ G, int ld,
                                      long row0, int k0, int tid, float* v)
{
#pragma unroll
    for (int p = 0; p < 4; ++p) {
        const int idx = tid + p * 256;
        const int r   = idx >> 3;
        const int c4  = (idx & 7) * 4;
        float4 t = *reinterpret_cast<const float4*>(&G[(row0 + r) * (long)ld + k0 + c4]);
        v[p * 4 + 0] = t.x; v[p * 4 + 1] = t.y;
        v[p * 4 + 2] = t.z; v[p * 4 + 3] = t.w;
    }
}
__device__ __forceinline__ void p_sts(const float* v, __half* Shi, __half* Slo, int tid)
{
#pragma unroll
    for (int p = 0; p < 4; ++p) {
        __half h[4], l[4];
#pragma unroll
        for (int j = 0; j < 4; ++j) split_h(v[p * 4 + j], h[j], l[j]);
        const int idx = tid + p * 256;
        const int r = idx >> 3, c = (idx & 7) * 4;
        *reinterpret_cast<__half2*>(&Shi[r * PROWH + c])     = __halves2half2(h[0], h[1]);
        *reinterpret_cast<__half2*>(&Shi[r * PROWH + c + 2]) = __halves2half2(h[2], h[3]);
        *reinterpret_cast<__half2*>(&Slo[r * PROWH + c])     = __halves2half2(l[0], l[1]);
        *reinterpret_cast<__half2*>(&Slo[r * PROWH + c + 2]) = __halves2half2(l[2], l[3]);
    }
}

__global__ __launch_bounds__(256)
void proj_both(const float* __restrict__ Vf, const float* __restrict__ Lf,
               const float* __restrict__ Wv, const float* __restrict__ bv,
               const float* __restrict__ Wl, const float* __restrict__ bl,
               __half* __restrict__ vph, __half* __restrict__ vpl,
               __half* __restrict__ lph, __half* __restrict__ lpl)
{
    extern __shared__ __half hsm[];
    const int z = blockIdx.z;
    const float* A    = z ? Lf : Vf;
    const float* B    = z ? Wl : Wv;
    const float* bias = z ? bl : bv;
    __half* Ch = z ? lph : vph;
    __half* Cl = z ? lpl : vpl;

    const int tid  = threadIdx.x;
    const int lane = tid & 31;
    const int wid  = tid >> 5;
    const int wm   = wid & 3;
    const int wn   = wid >> 2;
    const long m0  = (long)blockIdx.y * 128;
    const long n0  = (long)blockIdx.x * 128;
    const int lr   = lane >> 2;
    const int lc   = lane & 3;

    float acc[2][8][4];
#pragma unroll
    for (int i = 0; i < 2; ++i)
#pragma unroll
        for (int j = 0; j < 8; ++j)
#pragma unroll
            for (int q = 0; q < 4; ++q) acc[i][j][q] = 0.f;

    const int NIT = DIM / 32;   // 24
    float ra[16], rb[16];

    p_ldg(A, DIM, m0, 0, tid, ra);
    p_ldg(B, DIM, n0, 0, tid, rb);
    p_sts(ra, hsm,               hsm + PTILE_H,     tid);
    p_sts(rb, hsm + 2 * PTILE_H, hsm + 3 * PTILE_H, tid);
    p_ldg(A, DIM, m0, 32, tid, ra);
    p_ldg(B, DIM, n0, 32, tid, rb);

    for (int it = 0; it < NIT; ++it) {
        __syncthreads();
        if (it + 1 < NIT) {
            __half* st = hsm + ((it + 1) % 3) * PSTAGE_H;
            p_sts(ra, st,               st + PTILE_H,     tid);
            p_sts(rb, st + 2 * PTILE_H, st + 3 * PTILE_H, tid);
        }
        if (it + 2 < NIT) {
            p_ldg(A, DIM, m0, (it + 2) * 32, tid, ra);
            p_ldg(B, DIM, n0, (it + 2) * 32, tid, rb);
        }
        const __half* Ahi = hsm + (it % 3) * PSTAGE_H;
        const __half* Alo = Ahi + PTILE_H;
        const __half* Bhi = Ahi + 2 * PTILE_H;
        const __half* Blo = Ahi + 3 * PTILE_H;

#pragma unroll
        for (int ks = 0; ks < 2; ++ks) {
            const int kb = ks * 16;
            uint32_t ah[2][4], al[2][4];
#pragma unroll
            for (int mt = 0; mt < 2; ++mt) {
                const int mb = wm * 32 + mt * 16;
                const int o0 = (mb + lr)     * PROWH + kb + 2 * lc;
                const int o1 = (mb + 8 + lr) * PROWH + kb + 2 * lc;
                ah[mt][0] = lds_u32(&Ahi[o0]);
                ah[mt][1] = lds_u32(&Ahi[o1]);
                ah[mt][2] = lds_u32(&Ahi[o0 + 8]);
                ah[mt][3] = lds_u32(&Ahi[o1 + 8]);
                al[mt][0] = lds_u32(&Alo[o0]);
                al[mt][1] = lds_u32(&Alo[o1]);
                al[mt][2] = lds_u32(&Alo[o0 + 8]);
                al[mt][3] = lds_u32(&Alo[o1 + 8]);
            }
#pragma unroll
            for (int nt = 0; nt < 8; ++nt) {
                const int nb = wn * 64 + nt * 8;
                const int ob = (nb + lr) * PROWH + kb + 2 * lc;
                uint32_t bh[2], bl[2];
                bh[0] = lds_u32(&Bhi[ob]);
                bh[1] = lds_u32(&Bhi[ob + 8]);
                bl[0] = lds_u32(&Blo[ob]);
                bl[1] = lds_u32(&Blo[ob + 8]);
#pragma unroll
                for (int mt = 0; mt < 2; ++mt) {
                    mma16(acc[mt][nt], ah[mt], bh);
                    mma16(acc[mt][nt], ah[mt], bl);
                    mma16(acc[mt][nt], al[mt], bh);
                }
            }
        }
    }

    // epilogue: +bias, split to hi/lo fp16
#pragma unroll
    for (int mt = 0; mt < 2; ++mt) {
        const long r0 = m0 + wm * 32 + mt * 16 + lr;
#pragma unroll
        for (int nt = 0; nt < 8; ++nt) {
            const long c = n0 + wn * 64 + nt * 8 + lc * 2;
            float2 bb = *reinterpret_cast<const float2*>(&bias[c]);
            float v[4] = {acc[mt][nt][0] + bb.x, acc[mt][nt][1] + bb.y,
                          acc[mt][nt][2] + bb.x, acc[mt][nt][3] + bb.y};
            __half h[4], l[4];
#pragma unroll
            for (int q = 0; q < 4; ++q) split_h(v[q], h[q], l[q]);
            *reinterpret_cast<__half2*>(&Ch[r0 * DIM + c])       = __halves2half2(h[0], h[1]);
            *reinterpret_cast<__half2*>(&Ch[(r0 + 8) * DIM + c]) = __halves2half2(h[2], h[3]);
            *reinterpret_cast<__half2*>(&Cl[r0 * DIM + c])       = __halves2half2(l[0], l[1]);
            *reinterpret_cast<__half2*>(&Cl[(r0 + 8) * DIM + c]) = __halves2half2(l[2], l[3]);
        }
    }
}

// ---------------------------------------------------------------------------
// GEMM kernel wrappers
// ---------------------------------------------------------------------------
// sim[b] = (vph+vpl)(lph+lpl)^T, 3x, fp32 out.  grid (16,16,8), smem 122880
__global__ __launch_bounds__(256)
void sim_gemm(const __half* __restrict__ vph, const __half* __restrict__ vpl,
              const __half* __restrict__ lph, const __half* __restrict__ lpl,
              float* __restrict__ sim)
{
    extern __shared__ __half hsm[];
    const long b  = blockIdx.z;
    const long sF = (long)SEQ * DIM;
    const long sS = (long)SEQ * SEQ;
    gemm16_body<true, true, 3, 0, false>(
        vph + b * sF, vpl + b * sF, DIM,
        lph + b * sF, lpl + b * sF, DIM,
        sim + b * sS, nullptr, SEQ, DIM, nullptr, hsm);
}

// av/al, 1x, writes comb fp16.  grid (6,16,16), smem 81920, 2 CTAs/SM
__global__ __launch_bounds__(256, 2)
void avl_gemm(const __half* __restrict__ at,  const __half* __restrict__ att,
              const __half* __restrict__ vpt, const __half* __restrict__ lpt,
              __half* __restrict__ cb)
{
    extern __shared__ __half hsm[];
    const int z   = blockIdx.z;
    const long b  = z & 7;
    const long sS = (long)SEQ * SEQ;
    const long sF = (long)SEQ * DIM;
    const long sO = (long)SEQ * 2 * DIM;
    const __half* A = (z >> 3) ? (att + b * sS) : (at + b * sS);
    const __half* B = (z >> 3) ? (lpt + b * sF) : (vpt + b * sF);
    const long    co = b * sO + ((z >> 3) ? DIM : 0);
    gemm16_body<false, false, 4, 1, false>(
        A, nullptr, SEQ, B, nullptr, SEQ,
        nullptr, cb + co, 2 * DIM, SEQ, nullptr, hsm);
}

// out = cb @ Wo16^T + bo, 1x, fp32 out.  grid (6,128,1), smem 61440, 2 CTAs/SM
__global__ __launch_bounds__(256, 2)
void out_gemm(const __half* __restrict__ cb,
              const __half* __restrict__ wo, const float* __restrict__ bo,
              float* __restrict__ out)
{
    extern __shared__ __half hsm[];
    gemm16_body<false, false, 3, 0, true>(
        cb, nullptr, 2 * DIM, wo, nullptr, 2 * DIM,
        out, nullptr, DIM, 2 * DIM, bo, hsm);
}

// ---------------------------------------------------------------------------
// fp16 tiled transpose (proven 1.68 TB/s): dst[b][x][y] = src[b][y][x].
// src [R][C], dst [C][R].  block (32,8), grid (C/32, R/32, NB)
// ---------------------------------------------------------------------------
__global__ __launch_bounds__(256)
void transpose16(const __half* __restrict__ src, __half* __restrict__ dst,
                 int R, int C, long stride)
{
    __shared__ __half t[32][34];
    const long b  = blockIdx.z;
    const int  x0 = blockIdx.x * 32;
    const int  y0 = blockIdx.y * 32;
    const __half* s = src + b * stride;
    __half*       d = dst + b * stride;
    const int tx = threadIdx.x, ty = threadIdx.y;
#pragma unroll
    for (int i = 0; i < 4; ++i)
        t[ty + i * 8][tx] = s[(long)(y0 + ty + i * 8) * C + x0 + tx];
    __syncthreads();
#pragma unroll
    for (int i = 0; i < 4; ++i)
        d[(long)(x0 + ty + i * 8) * R + y0 + tx] = t[tx][ty + i * 8];
}

// vp^T and lp^T in one launch: z in [0,16): b = z&7, src/dst pair by z>>3.
__global__ __launch_bounds__(256)
void transpose_vl(const __half* __restrict__ vph, __half* __restrict__ vpt,
                  const __half* __restrict__ lph, __half* __restrict__ lpt)
{
    __shared__ __half t[32][34];
    const int z = blockIdx.z;
    const long b  = z & 7;
    const long stride = (long)SEQ * DIM;
    const __half* s = ((z >> 3) ? lph : vph) + b * stride;
    __half*       d = ((z >> 3) ? lpt : vpt) + b * stride;
    const int x0 = blockIdx.x * 32;
    const int y0 = blockIdx.y * 32;
    const int tx = threadIdx.x & 31, ty = threadIdx.x >> 5;
#pragma unroll
    for (int i = 0; i < 4; ++i)
        t[ty + i * 8][tx] = s[(long)(y0 + ty + i * 8) * DIM + x0 + tx];
    __syncthreads();
#pragma unroll
    for (int i = 0; i < 4; ++i)
        d[(long)(x0 + ty + i * 8) * SEQ + y0 + tx] = t[tx][ty + i * 8];
}

// Wo fp32 -> fp16
__global__ __launch_bounds__(256)
void wo_convert(const float* __restrict__ Wo, __half* __restrict__ wo16)
{
    const int i = blockIdx.x * 256 + threadIdx.x;
    float2 v = *reinterpret_cast<const float2*>(&Wo[i * 2]);
    *reinterpret_cast<__half2*>(&wo16[i * 2]) = __floats2half2_rn(v.x, v.y);
}

// ---------------------------------------------------------------------------
// Row softmax: sim fp32 -> attn fp16. One block per row of 2048.
// ---------------------------------------------------------------------------
__global__ __launch_bounds__(256)
void softmax2048h(const float* __restrict__ S, __half* __restrict__ O)
{
    const float* p = S + (long)blockIdx.x * 2048;
    __half*      o = O + (long)blockIdx.x * 2048;
    const int tid = threadIdx.x;

    float4 v0 = reinterpret_cast<const float4*>(p)[tid];
    float4 v1 = reinterpret_cast<const float4*>(p)[tid + 256];

    float mx = fmaxf(fmaxf(fmaxf(v0.x, v0.y), fmaxf(v0.z, v0.w)),
                     fmaxf(fmaxf(v1.x, v1.y), fmaxf(v1.z, v1.w)));

    __shared__ float red[8];
#pragma unroll
    for (int ofs = 16; ofs > 0; ofs >>= 1) mx = fmaxf(mx, __shfl_xor_sync(0xffffffffu, mx, ofs));
    if ((tid & 31) == 0) red[tid >> 5] = mx;
    __syncthreads();
    if (tid == 0) {
        float m = red[0];
#pragma unroll
        for (int w = 1; w < 8; ++w) m = fmaxf(m, red[w]);
        red[0] = m;
    }
    __syncthreads();
    mx = red[0];
    __syncthreads();

    v0.x = __expf(v0.x - mx); v0.y = __expf(v0.y - mx);
    v0.z = __expf(v0.z - mx); v0.w = __expf(v0.w - mx);
    v1.x = __expf(v1.x - mx); v1.y = __expf(v1.y - mx);
    v1.z = __expf(v1.z - mx); v1.w = __expf(v1.w - mx);

    float s = (v0.x + v0.y + v0.z + v0.w) + (v1.x + v1.y + v1.z + v1.w);
#pragma unroll
    for (int ofs = 16; ofs > 0; ofs >>= 1) s += __shfl_xor_sync(0xffffffffu, s, ofs);
    if ((tid & 31) == 0) red[tid >> 5] = s;
    __syncthreads();
    if (tid == 0) {
        float t = 0.f;
#pragma unroll
        for (int w = 0; w < 8; ++w) t += red[w];
        red[0] = t;
    }
    __syncthreads();
    const float inv = 1.0f / red[0];

    uint2 o0, o1;
    *reinterpret_cast<__half2*>(&o0.x) = __floats2half2_rn(v0.x * inv, v0.y * inv);
    *reinterpret_cast<__half2*>(&o0.y) = __floats2half2_rn(v0.z * inv, v0.w * inv);
    *reinterpret_cast<__half2*>(&o1.x) = __floats2half2_rn(v1.x * inv, v1.y * inv);
    *reinterpret_cast<__half2*>(&o1.y) = __floats2half2_rn(v1.z * inv, v1.w * inv);
    reinterpret_cast<uint2*>(o)[tid]       = o0;
    reinterpret_cast<uint2*>(o)[tid + 256] = o1;
}

// ---------------------------------------------------------------------------
// Launch
// ---------------------------------------------------------------------------
extern "C" void kernel_launch(void* const* d_in, const int* in_sizes, int n_in,
                              void* d_out, int out_size)
{
    const float* Vf = (const float*)d_in[0];
    const float* Lf = (const float*)d_in[1];
    const float* Wv = (const float*)d_in[2];
    const float* bv = (const float*)d_in[3];
    const float* Wl = (const float*)d_in[4];
    const float* bl = (const float*)d_in[5];
    const float* Wo = (const float*)d_in[6];
    const float* bo = (const float*)d_in[7];
    float* out = (float*)d_out;

    __half *vph, *vpl, *lph, *lpl, *vpt, *lpt, *at, *att, *cb, *wo16;
    float* sim;
    cudaGetSymbolAddress((void**)&vph, g_vph);
    cudaGetSymbolAddress((void**)&vpl, g_vpl);
    cudaGetSymbolAddress((void**)&lph, g_lph);
    cudaGetSymbolAddress((void**)&lpl, g_lpl);
    cudaGetSymbolAddress((void**)&vpt, g_vpt);
    cudaGetSymbolAddress((void**)&lpt, g_lpt);
    cudaGetSymbolAddress((void**)&sim, g_sim);
    cudaGetSymbolAddress((void**)&at,  g_at);
    cudaGetSymbolAddress((void**)&att, g_att);
    cudaGetSymbolAddress((void**)&cb,  g_cb);
    cudaGetSymbolAddress((void**)&wo16, g_wo16);

    cudaFuncSetAttribute(proj_both, cudaFuncAttributeMaxDynamicSharedMemorySize, PSMEM_B);
    cudaFuncSetAttribute(sim_gemm,  cudaFuncAttributeMaxDynamicSharedMemorySize, 4 * TILE16 * 3 * 2);
    cudaFuncSetAttribute(avl_gemm,  cudaFuncAttributeMaxDynamicSharedMemorySize, 2 * TILE16 * 4 * 2);
    cudaFuncSetAttribute(out_gemm,  cudaFuncAttributeMaxDynamicSharedMemorySize, 2 * TILE16 * 3 * 2);

    const dim3 blk(256);
    const long sS = (long)SEQ * SEQ;

    // Wo fp16 (independent)
    wo_convert<<<DIM * 2 * DIM / 512, blk>>>(Wo, wo16);
    // projections -> vp/lp hi+lo fp16
    proj_both<<<dim3(DIM/128, TOK/128, 2), blk, PSMEM_B>>>(
        Vf, Lf, Wv, bv, Wl, bl, vph, vpl, lph, lpl);
    // vp^T and lp^T, one launch
    transpose_vl<<<dim3(DIM/32, SEQ/32, 2 * BATCH), blk>>>(vph, vpt, lph, lpt);
    // sim (3x)
    sim_gemm<<<dim3(SEQ/128, SEQ/128, BATCH), blk, 4 * TILE16 * 3 * 2>>>(
        vph, vpl, lph, lpl, sim);
    // softmax -> attn fp16
    softmax2048h<<<TOK, blk>>>(sim, at);
    // attn^T fp16
    transpose16<<<dim3(SEQ/32, SEQ/32, BATCH), dim3(32, 8)>>>(at, att, SEQ, SEQ, sS);
    // av + al (1x) -> comb fp16
    avl_gemm<<<dim3(DIM/128, SEQ/128, 2 * BATCH), blk, 2 * TILE16 * 4 * 2>>>(
        at, att, vpt, lpt, cb);
    // out (1x)
    out_gemm<<<dim3(DIM/128, TOK/128, 1), blk, 2 * TILE16 * 3 * 2>>>(
        cb, wo16, bo, out);
}

// round 10
// speedup vs baseline: 1.1412x; 1.0332x over previous
#include <cuda_runtime.h>
#include <cuda_fp16.h>
#include <cstdint>

// ---------------------------------------------------------------------------
// B=8, L=2048, D=768.  All-fp16 cp.async GEMMs, 2 CTAs/SM, precision-tiered:
//   proj : 3xFP16 (inputs pre-split to fp16 hi/lo), writes vp/lp hi+lo
//   sim  : 3xFP16
//   av/al: 1xFP16 (transposed operands pre-built)
//   out  : 1xFP16
// ---------------------------------------------------------------------------
#define BATCH 8
#define SEQ   2048
#define DIM   768
#define TOK   (BATCH * SEQ)          // 16384

// Scratch (device globals: allocation-free rule)
__device__ __half g_vfh [TOK * DIM];                 // Vf hi   [16384,768]
__device__ __half g_vfl [TOK * DIM];
__device__ __half g_lfh [TOK * DIM];
__device__ __half g_lfl [TOK * DIM];
__device__ __half g_wvh [DIM * DIM];
__device__ __half g_wvl [DIM * DIM];
__device__ __half g_wlh [DIM * DIM];
__device__ __half g_wll [DIM * DIM];
__device__ __half g_vph [TOK * DIM];                 // vp hi
__device__ __half g_vpl [TOK * DIM];
__device__ __half g_lph [TOK * DIM];
__device__ __half g_lpl [TOK * DIM];
__device__ __half g_vpt [TOK * DIM];                 // vp^T [8][768][2048]
__device__ __half g_lpt [TOK * DIM];
__device__ float  g_sim [(long)BATCH * SEQ * SEQ];   // [8,2048,2048]
__device__ __half g_at  [(long)BATCH * SEQ * SEQ];   // attn
__device__ __half g_att [(long)BATCH * SEQ * SEQ];   // attn^T
__device__ __half g_cb  [(long)TOK * 2 * DIM];       // comb fp16 [16384,1536]
__device__ __half g_wo16[DIM * 2 * DIM];             // Wo fp16

// ---------------------------------------------------------------------------
// helpers
// ---------------------------------------------------------------------------
__device__ __forceinline__ uint32_t smem_u32(const void* p) {
    uint32_t a;
    asm("{ .reg .u64 t; cvta.to.shared.u64 t, %1; cvt.u32.u64 %0, t; }"
        : "=r"(a) : "l"(p));
    return a;
}
__device__ __forceinline__ void cp16(uint32_t s, const void* g) {
    asm volatile("cp.async.ca.shared.global [%0], [%1], 16;" :: "r"(s), "l"(g));
}
#define CP_COMMIT() asm volatile("cp.async.commit_group;" ::: "memory")
template<int N>
__device__ __forceinline__ void cp_wait() {
    asm volatile("cp.async.wait_group %0;" :: "n"(N) : "memory");
}
__device__ __forceinline__ void mma16(float* d, const uint32_t* a, const uint32_t* b) {
    asm volatile(
        "mma.sync.aligned.m16n8k16.row.col.f32.f16.f16.f32 "
        "{%0,%1,%2,%3}, {%4,%5,%6,%7}, {%8,%9}, {%0,%1,%2,%3};"
        : "+f"(d[0]), "+f"(d[1]), "+f"(d[2]), "+f"(d[3])
        : "r"(a[0]), "r"(a[1]), "r"(a[2]), "r"(a[3]), "r"(b[0]), "r"(b[1]));
}
__device__ __forceinline__ uint32_t lds_u32(const __half* p) {
    return *reinterpret_cast<const uint32_t*>(p);
}
__device__ __forceinline__ void split_h(float a, __half& h, __half& l) {
    h = __float2half_rn(a);
    l = __float2half_rn(a - __half2float(h));
}

// SMEM tile: 128 rows x 32 k halves, row stride 40 halves (80 B)
#define ROWH    40
#define TILE16  (128 * ROWH)          // halves per tile (10240 B)

// fp16 cp.async stage loader: 128 rows x 32 k from src[(row0+r)*ld + k0 + c]
__device__ __forceinline__ void load_stage16(__half* dst, const __half* __restrict__ src,
                                             int ld, long row0, int k0, int tid)
{
#pragma unroll
    for (int p = 0; p < 2; ++p) {
        const int idx = tid + p * 256;       // 0..511
        const int r   = idx >> 2;            // 0..127
        const int c8  = (idx & 3) * 8;       // 0,8,16,24
        cp16(smem_u32(&dst[r * ROWH + c8]), &src[(row0 + r) * (long)ld + k0 + c8]);
    }
}

// ---------------------------------------------------------------------------
// All-fp16 GEMM body: mma.sync m16n8k16, CTA tile 128x128, K-chunk 32,
// NST-stage cp.async pipeline.  C[m,n] = sum_k opA[m,k]*opB[n,k]
//   SA/SB: operand has hi+lo tiles.
//   WMODE: 0 = fp32 out, 1 = fp16 out, 2 = fp16 hi/lo split out
// ---------------------------------------------------------------------------
template<bool SA, bool SB, int NST, int WMODE, bool BIAS>
__device__ __forceinline__ void gemm16_body(
    const __half* __restrict__ Ah, const __half* __restrict__ Al, int lda,
    const __half* __restrict__ Bh, const __half* __restrict__ Bl, int ldb,
    float* __restrict__ Cf, __half* __restrict__ Ch, __half* __restrict__ Cl, int ldc,
    int K, const float* __restrict__ bias, __half* hsm)
{
    constexpr int NTIL = (SA ? 2 : 1) + (SB ? 2 : 1);
    constexpr int STG  = NTIL * TILE16;

    const int tid  = threadIdx.x;
    const int lane = tid & 31;
    const int wid  = tid >> 5;
    const int wm   = wid & 3;
    const int wn   = wid >> 2;
    const long m0  = (long)blockIdx.y * 128;
    const long n0  = (long)blockIdx.x * 128;
    const int lr   = lane >> 2;
    const int lc   = lane & 3;

    float acc[2][8][4];
#pragma unroll
    for (int i = 0; i < 2; ++i)
#pragma unroll
        for (int j = 0; j < 8; ++j)
#pragma unroll
            for (int q = 0; q < 4; ++q) acc[i][j][q] = 0.f;

    const int NIT = K / 32;

    auto issue = [&](int st) {
        if (st < NIT) {
            __half* s = hsm + (st % NST) * STG;
            const int k0 = st * 32;
            load_stage16(s, Ah, lda, m0, k0, tid);
            if (SA) load_stage16(s + TILE16, Al, lda, m0, k0, tid);
            __half* sb = s + (SA ? 2 : 1) * TILE16;
            load_stage16(sb, Bh, ldb, n0, k0, tid);
            if (SB) load_stage16(sb + TILE16, Bl, ldb, n0, k0, tid);
        }
        CP_COMMIT();
    };

#pragma unroll
    for (int s = 0; s < NST - 1; ++s) issue(s);

    for (int it = 0; it < NIT; ++it) {
        cp_wait<NST - 2>();
        __syncthreads();
        issue(it + NST - 1);

        const __half* At  = hsm + (it % NST) * STG;
        const __half* AtL = At + TILE16;
        const __half* Bt  = At + (SA ? 2 : 1) * TILE16;
        const __half* BtL = Bt + TILE16;

#pragma unroll
        for (int ks = 0; ks < 2; ++ks) {
            const int kb = ks * 16;
            uint32_t ah[2][4], al[2][4];
#pragma unroll
            for (int mt = 0; mt < 2; ++mt) {
                const int mb = wm * 32 + mt * 16;
                const int o0 = (mb + lr)     * ROWH + kb + 2 * lc;
                const int o1 = (mb + 8 + lr) * ROWH + kb + 2 * lc;
                ah[mt][0] = lds_u32(&At[o0]);
                ah[mt][1] = lds_u32(&At[o1]);
                ah[mt][2] = lds_u32(&At[o0 + 8]);
                ah[mt][3] = lds_u32(&At[o1 + 8]);
                if (SA) {
                    al[mt][0] = lds_u32(&AtL[o0]);
                    al[mt][1] = lds_u32(&AtL[o1]);
                    al[mt][2] = lds_u32(&AtL[o0 + 8]);
                    al[mt][3] = lds_u32(&AtL[o1 + 8]);
                }
            }
#pragma unroll
            for (int nt = 0; nt < 8; ++nt) {
                const int nb = wn * 64 + nt * 8;
                const int ob = (nb + lr) * ROWH + kb + 2 * lc;
                uint32_t bh[2], bl[2];
                bh[0] = lds_u32(&Bt[ob]);
                bh[1] = lds_u32(&Bt[ob + 8]);
                if (SB) {
                    bl[0] = lds_u32(&BtL[ob]);
                    bl[1] = lds_u32(&BtL[ob + 8]);
                }
#pragma unroll
                for (int mt = 0; mt < 2; ++mt) {
                    mma16(acc[mt][nt], ah[mt], bh);
                    if (SB) mma16(acc[mt][nt], ah[mt], bl);
                    if (SA) mma16(acc[mt][nt], al[mt], bh);
                }
            }
        }
    }

    // ---- epilogue ----
#pragma unroll
    for (int mt = 0; mt < 2; ++mt) {
        const long r0 = m0 + wm * 32 + mt * 16 + lr;
#pragma unroll
        for (int nt = 0; nt < 8; ++nt) {
            const long c = n0 + wn * 64 + nt * 8 + lc * 2;
            float v[4] = {acc[mt][nt][0], acc[mt][nt][1], acc[mt][nt][2], acc[mt][nt][3]};
            if (BIAS) {
                float2 bb = *reinterpret_cast<const float2*>(&bias[c]);
                v[0] += bb.x; v[1] += bb.y; v[2] += bb.x; v[3] += bb.y;
            }
            if (WMODE == 0) {
                *reinterpret_cast<float2*>(&Cf[r0 * ldc + c])       = make_float2(v[0], v[1]);
                *reinterpret_cast<float2*>(&Cf[(r0 + 8) * ldc + c]) = make_float2(v[2], v[3]);
            } else if (WMODE == 1) {
                *reinterpret_cast<__half2*>(&Ch[r0 * ldc + c])       = __floats2half2_rn(v[0], v[1]);
                *reinterpret_cast<__half2*>(&Ch[(r0 + 8) * ldc + c]) = __floats2half2_rn(v[2], v[3]);
            } else {
                __half h[4], l[4];
#pragma unroll
                for (int q = 0; q < 4; ++q) split_h(v[q], h[q], l[q]);
                *reinterpret_cast<__half2*>(&Ch[r0 * ldc + c])       = __halves2half2(h[0], h[1]);
                *reinterpret_cast<__half2*>(&Ch[(r0 + 8) * ldc + c]) = __halves2half2(h[2], h[3]);
                *reinterpret_cast<__half2*>(&Cl[r0 * ldc + c])       = __halves2half2(l[0], l[1]);
                *reinterpret_cast<__half2*>(&Cl[(r0 + 8) * ldc + c]) = __halves2half2(l[2], l[3]);
            }
        }
    }
}

// ---------------------------------------------------------------------------
// GEMM kernel wrappers (all 2 CTAs/SM)
// ---------------------------------------------------------------------------
// proj: vp/lp = X @ W^T + b, 3x, fp16 hi/lo out.  z: 0=vision, 1=language.
// grid (6,128,2), smem 81920
__global__ __launch_bounds__(256, 2)
void proj_gemm(const __half* __restrict__ vfh, const __half* __restrict__ vfl,
               const __half* __restrict__ lfh, const __half* __restrict__ lfl,
               const __half* __restrict__ wvh, const __half* __restrict__ wvl,
               const __half* __restrict__ wlh, const __half* __restrict__ wll,
               const float* __restrict__ bv, const float* __restrict__ bl,
               __half* __restrict__ vph, __half* __restrict__ vpl,
               __half* __restrict__ lph, __half* __restrict__ lpl)
{
    extern __shared__ __half hsm[];
    const int z = blockIdx.z;
    gemm16_body<true, true, 2, 2, true>(
        z ? lfh : vfh, z ? lfl : vfl, DIM,
        z ? wlh : wvh, z ? wll : wvl, DIM,
        nullptr, z ? lph : vph, z ? lpl : vpl, DIM,
        DIM, z ? bl : bv, hsm);
}

// sim[b] = (vph+vpl)(lph+lpl)^T, 3x, fp32 out.  grid (16,16,8), smem 81920
__global__ __launch_bounds__(256, 2)
void sim_gemm(const __half* __restrict__ vph, const __half* __restrict__ vpl,
              const __half* __restrict__ lph, const __half* __restrict__ lpl,
              float* __restrict__ sim)
{
    extern __shared__ __half hsm[];
    const long b  = blockIdx.z;
    const long sF = (long)SEQ * DIM;
    const long sS = (long)SEQ * SEQ;
    gemm16_body<true, true, 2, 0, false>(
        vph + b * sF, vpl + b * sF, DIM,
        lph + b * sF, lpl + b * sF, DIM,
        sim + b * sS, nullptr, nullptr, SEQ, DIM, nullptr, hsm);
}

// av/al, 1x, writes comb fp16.  grid (6,16,16), smem 81920
__global__ __launch_bounds__(256, 2)
void avl_gemm(const __half* __restrict__ at,  const __half* __restrict__ att,
              const __half* __restrict__ vpt, const __half* __restrict__ lpt,
              __half* __restrict__ cb)
{
    extern __shared__ __half hsm[];
    const int z   = blockIdx.z;
    const long b  = z & 7;
    const long sS = (long)SEQ * SEQ;
    const long sF = (long)SEQ * DIM;
    const long sO = (long)SEQ * 2 * DIM;
    const __half* A = (z >> 3) ? (att + b * sS) : (at + b * sS);
    const __half* B = (z >> 3) ? (lpt + b * sF) : (vpt + b * sF);
    const long    co = b * sO + ((z >> 3) ? DIM : 0);
    gemm16_body<false, false, 4, 1, false>(
        A, nullptr, SEQ, B, nullptr, SEQ,
        nullptr, cb + co, nullptr, 2 * DIM, SEQ, nullptr, hsm);
}

// out = cb @ Wo16^T + bo, 1x, fp32 out.  grid (6,128,1), smem 61440
__global__ __launch_bounds__(256, 2)
void out_gemm(const __half* __restrict__ cb,
              const __half* __restrict__ wo, const float* __restrict__ bo,
              float* __restrict__ out)
{
    extern __shared__ __half hsm[];
    gemm16_body<false, false, 3, 0, true>(
        cb, nullptr, 2 * DIM, wo, nullptr, 2 * DIM,
        out, nullptr, nullptr, DIM, 2 * DIM, bo, hsm);
}

// ---------------------------------------------------------------------------
// fp32 -> fp16 hi/lo split (elementwise), float4 granularity
// ---------------------------------------------------------------------------
__global__ __launch_bounds__(256)
void convert_split(const float* __restrict__ src, __half* __restrict__ h,
                   __half* __restrict__ l)
{
    const long i = (long)blockIdx.x * 256 + threadIdx.x;
    float4 v = reinterpret_cast<const float4*>(src)[i];
    __half hh[4], ll[4];
    split_h(v.x, hh[0], ll[0]); split_h(v.y, hh[1], ll[1]);
    split_h(v.z, hh[2], ll[2]); split_h(v.w, hh[3], ll[3]);
    uint2 ho, lo;
    *reinterpret_cast<__half2*>(&ho.x) = __halves2half2(hh[0], hh[1]);
    *reinterpret_cast<__half2*>(&ho.y) = __halves2half2(hh[2], hh[3]);
    *reinterpret_cast<__half2*>(&lo.x) = __halves2half2(ll[0], ll[1]);
    *reinterpret_cast<__half2*>(&lo.y) = __halves2half2(ll[2], ll[3]);
    reinterpret_cast<uint2*>(h)[i] = ho;
    reinterpret_cast<uint2*>(l)[i] = lo;
}

// Wo fp32 -> fp16
__global__ __launch_bounds__(256)
void wo_convert(const float* __restrict__ Wo, __half* __restrict__ wo16)
{
    const int i = blockIdx.x * 256 + threadIdx.x;
    float2 v = *reinterpret_cast<const float2*>(&Wo[i * 2]);
    *reinterpret_cast<__half2*>(&wo16[i * 2]) = __floats2half2_rn(v.x, v.y);
}

// ---------------------------------------------------------------------------
// fp16 tiled transposes
// ---------------------------------------------------------------------------
__global__ __launch_bounds__(256)
void transpose16(const __half* __restrict__ src, __half* __restrict__ dst,
                 int R, int C, long stride)
{
    __shared__ __half t[32][34];
    const long b  = blockIdx.z;
    const int  x0 = blockIdx.x * 32;
    const int  y0 = blockIdx.y * 32;
    const __half* s = src + b * stride;
    __half*       d = dst + b * stride;
    const int tx = threadIdx.x, ty = threadIdx.y;
#pragma unroll
    for (int i = 0; i < 4; ++i)
        t[ty + i * 8][tx] = s[(long)(y0 + ty + i * 8) * C + x0 + tx];
    __syncthreads();
#pragma unroll
    for (int i = 0; i < 4; ++i)
        d[(long)(x0 + ty + i * 8) * R + y0 + tx] = t[tx][ty + i * 8];
}

// vp^T and lp^T in one launch: z in [0,16): b = z&7, pair by z>>3.
__global__ __launch_bounds__(256)
void transpose_vl(const __half* __restrict__ vph, __half* __restrict__ vpt,
                  const __half* __restrict__ lph, __half* __restrict__ lpt)
{
    __shared__ __half t[32][34];
    const int z = blockIdx.z;
    const long b  = z & 7;
    const long stride = (long)SEQ * DIM;
    const __half* s = ((z >> 3) ? lph : vph) + b * stride;
    __half*       d = ((z >> 3) ? lpt : vpt) + b * stride;
    const int x0 = blockIdx.x * 32;
    const int y0 = blockIdx.y * 32;
    const int tx = threadIdx.x & 31, ty = threadIdx.x >> 5;
#pragma unroll
    for (int i = 0; i < 4; ++i)
        t[ty + i * 8][tx] = s[(long)(y0 + ty + i * 8) * DIM + x0 + tx];
    __syncthreads();
#pragma unroll
    for (int i = 0; i < 4; ++i)
        d[(long)(x0 + ty + i * 8) * SEQ + y0 + tx] = t[tx][ty + i * 8];
}

// ---------------------------------------------------------------------------
// Row softmax: sim fp32 -> attn fp16. One block per row of 2048.
// ---------------------------------------------------------------------------
__global__ __launch_bounds__(256)
void softmax2048h(const float* __restrict__ S, __half* __restrict__ O)
{
    const float* p = S + (long)blockIdx.x * 2048;
    __half*      o = O + (long)blockIdx.x * 2048;
    const int tid = threadIdx.x;

    float4 v0 = reinterpret_cast<const float4*>(p)[tid];
    float4 v1 = reinterpret_cast<const float4*>(p)[tid + 256];

    float mx = fmaxf(fmaxf(fmaxf(v0.x, v0.y), fmaxf(v0.z, v0.w)),
                     fmaxf(fmaxf(v1.x, v1.y), fmaxf(v1.z, v1.w)));

    __shared__ float red[8];
#pragma unroll
    for (int ofs = 16; ofs > 0; ofs >>= 1) mx = fmaxf(mx, __shfl_xor_sync(0xffffffffu, mx, ofs));
    if ((tid & 31) == 0) red[tid >> 5] = mx;
    __syncthreads();
    if (tid == 0) {
        float m = red[0];
#pragma unroll
        for (int w = 1; w < 8; ++w) m = fmaxf(m, red[w]);
        red[0] = m;
    }
    __syncthreads();
    mx = red[0];
    __syncthreads();

    v0.x = __expf(v0.x - mx); v0.y = __expf(v0.y - mx);
    v0.z = __expf(v0.z - mx); v0.w = __expf(v0.w - mx);
    v1.x = __expf(v1.x - mx); v1.y = __expf(v1.y - mx);
    v1.z = __expf(v1.z - mx); v1.w = __expf(v1.w - mx);

    float s = (v0.x + v0.y + v0.z + v0.w) + (v1.x + v1.y + v1.z + v1.w);
#pragma unroll
    for (int ofs = 16; ofs > 0; ofs >>= 1) s += __shfl_xor_sync(0xffffffffu, s, ofs);
    if ((tid & 31) == 0) red[tid >> 5] = s;
    __syncthreads();
    if (tid == 0) {
        float t = 0.f;
#pragma unroll
        for (int w = 0; w < 8; ++w) t += red[w];
        red[0] = t;
    }
    __syncthreads();
    const float inv = 1.0f / red[0];

    uint2 o0, o1;
    *reinterpret_cast<__half2*>(&o0.x) = __floats2half2_rn(v0.x * inv, v0.y * inv);
    *reinterpret_cast<__half2*>(&o0.y) = __floats2half2_rn(v0.z * inv, v0.w * inv);
    *reinterpret_cast<__half2*>(&o1.x) = __floats2half2_rn(v1.x * inv, v1.y * inv);
    *reinterpret_cast<__half2*>(&o1.y) = __floats2half2_rn(v1.z * inv, v1.w * inv);
    reinterpret_cast<uint2*>(o)[tid]       = o0;
    reinterpret_cast<uint2*>(o)[tid + 256] = o1;
}

// ---------------------------------------------------------------------------
// Launch
// ---------------------------------------------------------------------------
extern "C" void kernel_launch(void* const* d_in, const int* in_sizes, int n_in,
                              void* d_out, int out_size)
{
    const float* Vf = (const float*)d_in[0];
    const float* Lf = (const float*)d_in[1];
    const float* Wv = (const float*)d_in[2];
    const float* bv = (const float*)d_in[3];
    const float* Wl = (const float*)d_in[4];
    const float* bl = (const float*)d_in[5];
    const float* Wo = (const float*)d_in[6];
    const float* bo = (const float*)d_in[7];
    float* out = (float*)d_out;

    __half *vfh, *vfl, *lfh, *lfl, *wvh, *wvl, *wlh, *wll;
    __half *vph, *vpl, *lph, *lpl, *vpt, *lpt, *at, *att, *cb, *wo16;
    float* sim;
    cudaGetSymbolAddress((void**)&vfh, g_vfh);
    cudaGetSymbolAddress((void**)&vfl, g_vfl);
    cudaGetSymbolAddress((void**)&lfh, g_lfh);
    cudaGetSymbolAddress((void**)&lfl, g_lfl);
    cudaGetSymbolAddress((void**)&wvh, g_wvh);
    cudaGetSymbolAddress((void**)&wvl, g_wvl);
    cudaGetSymbolAddress((void**)&wlh, g_wlh);
    cudaGetSymbolAddress((void**)&wll, g_wll);
    cudaGetSymbolAddress((void**)&vph, g_vph);
    cudaGetSymbolAddress((void**)&vpl, g_vpl);
    cudaGetSymbolAddress((void**)&lph, g_lph);
    cudaGetSymbolAddress((void**)&lpl, g_lpl);
    cudaGetSymbolAddress((void**)&vpt, g_vpt);
    cudaGetSymbolAddress((void**)&lpt, g_lpt);
    cudaGetSymbolAddress((void**)&sim, g_sim);
    cudaGetSymbolAddress((void**)&at,  g_at);
    cudaGetSymbolAddress((void**)&att, g_att);
    cudaGetSymbolAddress((void**)&cb,  g_cb);
    cudaGetSymbolAddress((void**)&wo16, g_wo16);

    const int S2 = 4 * TILE16 * 2 * 2;   // 81920 (proj, sim)
    const int S4 = 2 * TILE16 * 4 * 2;   // 81920 (avl)
    const int S3 = 2 * TILE16 * 3 * 2;   // 61440 (out)
    cudaFuncSetAttribute(proj_gemm, cudaFuncAttributeMaxDynamicSharedMemorySize, S2);
    cudaFuncSetAttribute(sim_gemm,  cudaFuncAttributeMaxDynamicSharedMemorySize, S2);
    cudaFuncSetAttribute(avl_gemm,  cudaFuncAttributeMaxDynamicSharedMemorySize, S4);
    cudaFuncSetAttribute(out_gemm,  cudaFuncAttributeMaxDynamicSharedMemorySize, S3);

    const dim3 blk(256);
    const long sS = (long)SEQ * SEQ;

    // input conversions
    wo_convert<<<DIM * 2 * DIM / 512, blk>>>(Wo, wo16);
    convert_split<<<TOK * DIM / 1024, blk>>>(Vf, vfh, vfl);
    convert_split<<<TOK * DIM / 1024, blk>>>(Lf, lfh, lfl);
    convert_split<<<DIM * DIM / 1024, blk>>>(Wv, wvh, wvl);
    convert_split<<<DIM * DIM / 1024, blk>>>(Wl, wlh, wll);
    // projections (3x) -> vp/lp hi+lo fp16
    proj_gemm<<<dim3(DIM/128, TOK/128, 2), blk, S2>>>(
        vfh, vfl, lfh, lfl, wvh, wvl, wlh, wll, bv, bl, vph, vpl, lph, lpl);
    // vp^T and lp^T, one launch
    transpose_vl<<<dim3(DIM/32, SEQ/32, 2 * BATCH), blk>>>(vph, vpt, lph, lpt);
    // sim (3x)
    sim_gemm<<<dim3(SEQ/128, SEQ/128, BATCH), blk, S2>>>(vph, vpl, lph, lpl, sim);
    // softmax -> attn fp16
    softmax2048h<<<TOK, blk>>>(sim, at);
    // attn^T fp16
    transpose16<<<dim3(SEQ/32, SEQ/32, BATCH), dim3(32, 8)>>>(at, att, SEQ, SEQ, sS);
    // av + al (1x) -> comb fp16
    avl_gemm<<<dim3(DIM/128, SEQ/128, 2 * BATCH), blk, S4>>>(at, att, vpt, lpt, cb);
    // out (1x)
    out_gemm<<<dim3(DIM/128, TOK/128, 1), blk, S3>>>(cb, wo16, bo, out);
}

// round 11
// speedup vs baseline: 1.2138x; 1.0637x over previous
#include <cuda_runtime.h>
#include <cuda_fp16.h>
#include <cstdint>

// ---------------------------------------------------------------------------
// B=8, L=2048, D=768.  All-fp16 cp.async GEMMs with ldmatrix fragments,
// 2 CTAs/SM, precision-tiered:
//   proj : 3xFP16 (inputs pre-split to fp16 hi/lo), writes vp/lp hi+lo
//   sim  : 3xFP16
//   av/al: 1xFP16 (transposed operands pre-built)
//   out  : 1xFP16
// ---------------------------------------------------------------------------
#define BATCH 8
#define SEQ   2048
#define DIM   768
#define TOK   (BATCH * SEQ)          // 16384

// Scratch (device globals: allocation-free rule)
__device__ __half g_vfh [TOK * DIM];                 // Vf hi   [16384,768]
__device__ __half g_vfl [TOK * DIM];
__device__ __half g_lfh [TOK * DIM];
__device__ __half g_lfl [TOK * DIM];
__device__ __half g_wvh [DIM * DIM];
__device__ __half g_wvl [DIM * DIM];
__device__ __half g_wlh [DIM * DIM];
__device__ __half g_wll [DIM * DIM];
__device__ __half g_vph [TOK * DIM];                 // vp hi
__device__ __half g_vpl [TOK * DIM];
__device__ __half g_lph [TOK * DIM];
__device__ __half g_lpl [TOK * DIM];
__device__ __half g_vpt [TOK * DIM];                 // vp^T [8][768][2048]
__device__ __half g_lpt [TOK * DIM];
__device__ float  g_sim [(long)BATCH * SEQ * SEQ];   // [8,2048,2048]
__device__ __half g_at  [(long)BATCH * SEQ * SEQ];   // attn
__device__ __half g_att [(long)BATCH * SEQ * SEQ];   // attn^T
__device__ __half g_cb  [(long)TOK * 2 * DIM];       // comb fp16 [16384,1536]
__device__ __half g_wo16[DIM * 2 * DIM];             // Wo fp16

// ---------------------------------------------------------------------------
// helpers
// ---------------------------------------------------------------------------
__device__ __forceinline__ uint32_t smem_u32(const void* p) {
    uint32_t a;
    asm("{ .reg .u64 t; cvta.to.shared.u64 t, %1; cvt.u32.u64 %0, t; }"
        : "=r"(a) : "l"(p));
    return a;
}
__device__ __forceinline__ void cp16(uint32_t s, const void* g) {
    asm volatile("cp.async.ca.shared.global [%0], [%1], 16;" :: "r"(s), "l"(g));
}
#define CP_COMMIT() asm volatile("cp.async.commit_group;" ::: "memory")
template<int N>
__device__ __forceinline__ void cp_wait() {
    asm volatile("cp.async.wait_group %0;" :: "n"(N) : "memory");
}
__device__ __forceinline__ void mma16(float* d, const uint32_t* a, const uint32_t* b) {
    asm volatile(
        "mma.sync.aligned.m16n8k16.row.col.f32.f16.f16.f32 "
        "{%0,%1,%2,%3}, {%4,%5,%6,%7}, {%8,%9}, {%0,%1,%2,%3};"
        : "+f"(d[0]), "+f"(d[1]), "+f"(d[2]), "+f"(d[3])
        : "r"(a[0]), "r"(a[1]), "r"(a[2]), "r"(a[3]), "r"(b[0]), "r"(b[1]));
}
#define LDM4(r, addr)                                                        \
    asm volatile("ldmatrix.sync.aligned.m8n8.x4.shared.b16 "                 \
                 "{%0,%1,%2,%3}, [%4];"                                      \
                 : "=r"((r)[0]), "=r"((r)[1]), "=r"((r)[2]), "=r"((r)[3])    \
                 : "r"(addr))
__device__ __forceinline__ void split_h(float a, __half& h, __half& l) {
    h = __float2half_rn(a);
    l = __float2half_rn(a - __half2float(h));
}

// SMEM tile: 128 rows x 32 k halves, row stride 40 halves (80 B, 16B-aligned)
#define ROWH    40
#define TILE16  (128 * ROWH)          // halves per tile (10240 B)

// fp16 cp.async stage loader: 128 rows x 32 k from src[(row0+r)*ld + k0 + c]
__device__ __forceinline__ void load_stage16(__half* dst, const __half* __restrict__ src,
                                             int ld, long row0, int k0, int tid)
{
#pragma unroll
    for (int p = 0; p < 2; ++p) {
        const int idx = tid + p * 256;       // 0..511
        const int r   = idx >> 2;            // 0..127
        const int c8  = (idx & 3) * 8;       // 0,8,16,24
        cp16(smem_u32(&dst[r * ROWH + c8]), &src[(row0 + r) * (long)ld + k0 + c8]);
    }
}

// ---------------------------------------------------------------------------
// All-fp16 GEMM body: mma.sync m16n8k16 + ldmatrix fragments,
// CTA tile 128x128, K-chunk 32, NST-stage cp.async pipeline.
//   C[m,n] = sum_k opA[m,k]*opB[n,k]
//   SA/SB: operand has hi+lo tiles.
//   WMODE: 0 = fp32 out, 1 = fp16 out, 2 = fp16 hi/lo split out
// ---------------------------------------------------------------------------
template<bool SA, bool SB, int NST, int WMODE, bool BIAS>
__device__ __forceinline__ void gemm16_body(
    const __half* __restrict__ Ah, const __half* __restrict__ Al, int lda,
    const __half* __restrict__ Bh, const __half* __restrict__ Bl, int ldb,
    float* __restrict__ Cf, __half* __restrict__ Ch, __half* __restrict__ Cl, int ldc,
    int K, const float* __restrict__ bias, __half* hsm)
{
    constexpr int NTIL = (SA ? 2 : 1) + (SB ? 2 : 1);
    constexpr int STG  = NTIL * TILE16;

    const int tid  = threadIdx.x;
    const int lane = tid & 31;
    const int wid  = tid >> 5;
    const int wm   = wid & 3;
    const int wn   = wid >> 2;
    const long m0  = (long)blockIdx.y * 128;
    const long n0  = (long)blockIdx.x * 128;
    const int lr   = lane >> 2;
    const int lc   = lane & 3;

    // ldmatrix per-lane offset (halves): row = (lane&15), col-group = (lane>>4)*8
    const uint32_t sb32 = smem_u32(hsm);
    const int loff  = (lane & 15) * ROWH + (lane >> 4) * 8;
    const int aoff0 = (wm * 32) * ROWH + loff;
    const int boff0 = (wn * 64) * ROWH + loff;

    float acc[2][8][4];
#pragma unroll
    for (int i = 0; i < 2; ++i)
#pragma unroll
        for (int j = 0; j < 8; ++j)
#pragma unroll
            for (int q = 0; q < 4; ++q) acc[i][j][q] = 0.f;

    const int NIT = K / 32;

    auto issue = [&](int st) {
        if (st < NIT) {
            __half* s = hsm + (st % NST) * STG;
            const int k0 = st * 32;
            load_stage16(s, Ah, lda, m0, k0, tid);
            if (SA) load_stage16(s + TILE16, Al, lda, m0, k0, tid);
            __half* sb = s + (SA ? 2 : 1) * TILE16;
            load_stage16(sb, Bh, ldb, n0, k0, tid);
            if (SB) load_stage16(sb + TILE16, Bl, ldb, n0, k0, tid);
        }
        CP_COMMIT();
    };

#pragma unroll
    for (int s = 0; s < NST - 1; ++s) issue(s);

    for (int it = 0; it < NIT; ++it) {
        cp_wait<NST - 2>();
        __syncthreads();
        issue(it + NST - 1);

        const int stA  = (it % NST) * STG;          // halves
        const int stAl = stA + TILE16;
        const int stB  = stA + (SA ? 2 : 1) * TILE16;
        const int stBl = stB + TILE16;

#pragma unroll
        for (int ks = 0; ks < 2; ++ks) {
            const int kb = ks * 16;
            uint32_t ah[2][4], al[2][4];
#pragma unroll
            for (int mt = 0; mt < 2; ++mt) {
                const int ao = aoff0 + mt * 16 * ROWH + kb;
                LDM4(ah[mt], sb32 + (uint32_t)(stA + ao) * 2);
                if (SA) LDM4(al[mt], sb32 + (uint32_t)(stAl + ao) * 2);
            }
#pragma unroll
            for (int ntg = 0; ntg < 4; ++ntg) {
                const int bo = boff0 + ntg * 16 * ROWH + kb;
                uint32_t bh4[4], bl4[4];
                LDM4(bh4, sb32 + (uint32_t)(stB + bo) * 2);
                if (SB) LDM4(bl4, sb32 + (uint32_t)(stBl + bo) * 2);
#pragma unroll
                for (int sub = 0; sub < 2; ++sub) {
                    const int nt = ntg * 2 + sub;
                    uint32_t bh[2] = {bh4[sub], bh4[2 + sub]};
                    uint32_t bl[2];
                    if (SB) { bl[0] = bl4[sub]; bl[1] = bl4[2 + sub]; }
#pragma unroll
                    for (int mt = 0; mt < 2; ++mt) {
                        mma16(acc[mt][nt], ah[mt], bh);
                        if (SB) mma16(acc[mt][nt], ah[mt], bl);
                        if (SA) mma16(acc[mt][nt], al[mt], bh);
                    }
                }
            }
        }
    }

    // ---- epilogue ----
#pragma unroll
    for (int mt = 0; mt < 2; ++mt) {
        const long r0 = m0 + wm * 32 + mt * 16 + lr;
#pragma unroll
        for (int nt = 0; nt < 8; ++nt) {
            const long c = n0 + wn * 64 + nt * 8 + lc * 2;
            float v[4] = {acc[mt][nt][0], acc[mt][nt][1], acc[mt][nt][2], acc[mt][nt][3]};
            if (BIAS) {
                float2 bb = *reinterpret_cast<const float2*>(&bias[c]);
                v[0] += bb.x; v[1] += bb.y; v[2] += bb.x; v[3] += bb.y;
            }
            if (WMODE == 0) {
                *reinterpret_cast<float2*>(&Cf[r0 * ldc + c])       = make_float2(v[0], v[1]);
                *reinterpret_cast<float2*>(&Cf[(r0 + 8) * ldc + c]) = make_float2(v[2], v[3]);
            } else if (WMODE == 1) {
                *reinterpret_cast<__half2*>(&Ch[r0 * ldc + c])       = __floats2half2_rn(v[0], v[1]);
                *reinterpret_cast<__half2*>(&Ch[(r0 + 8) * ldc + c]) = __floats2half2_rn(v[2], v[3]);
            } else {
                __half h[4], l[4];
#pragma unroll
                for (int q = 0; q < 4; ++q) split_h(v[q], h[q], l[q]);
                *reinterpret_cast<__half2*>(&Ch[r0 * ldc + c])       = __halves2half2(h[0], h[1]);
                *reinterpret_cast<__half2*>(&Ch[(r0 + 8) * ldc + c]) = __halves2half2(h[2], h[3]);
                *reinterpret_cast<__half2*>(&Cl[r0 * ldc + c])       = __halves2half2(l[0], l[1]);
                *reinterpret_cast<__half2*>(&Cl[(r0 + 8) * ldc + c]) = __halves2half2(l[2], l[3]);
            }
        }
    }
}

// ---------------------------------------------------------------------------
// GEMM kernel wrappers (all 2 CTAs/SM)
// ---------------------------------------------------------------------------
__global__ __launch_bounds__(256, 2)
void proj_gemm(const __half* __restrict__ vfh, const __half* __restrict__ vfl,
               const __half* __restrict__ lfh, const __half* __restrict__ lfl,
               const __half* __restrict__ wvh, const __half* __restrict__ wvl,
               const __half* __restrict__ wlh, const __half* __restrict__ wll,
               const float* __restrict__ bv, const float* __restrict__ bl,
               __half* __restrict__ vph, __half* __restrict__ vpl,
               __half* __restrict__ lph, __half* __restrict__ lpl)
{
    extern __shared__ __half hsm[];
    const int z = blockIdx.z;
    gemm16_body<true, true, 2, 2, true>(
        z ? lfh : vfh, z ? lfl : vfl, DIM,
        z ? wlh : wvh, z ? wll : wvl, DIM,
        nullptr, z ? lph : vph, z ? lpl : vpl, DIM,
        DIM, z ? bl : bv, hsm);
}

__global__ __launch_bounds__(256, 2)
void sim_gemm(const __half* __restrict__ vph, const __half* __restrict__ vpl,
              const __half* __restrict__ lph, const __half* __restrict__ lpl,
              float* __restrict__ sim)
{
    extern __shared__ __half hsm[];
    const long b  = blockIdx.z;
    const long sF = (long)SEQ * DIM;
    const long sS = (long)SEQ * SEQ;
    gemm16_body<true, true, 2, 0, false>(
        vph + b * sF, vpl + b * sF, DIM,
        lph + b * sF, lpl + b * sF, DIM,
        sim + b * sS, nullptr, nullptr, SEQ, DIM, nullptr, hsm);
}

__global__ __launch_bounds__(256, 2)
void avl_gemm(const __half* __restrict__ at,  const __half* __restrict__ att,
              const __half* __restrict__ vpt, const __half* __restrict__ lpt,
              __half* __restrict__ cb)
{
    extern __shared__ __half hsm[];
    const int z   = blockIdx.z;
    const long b  = z & 7;
    const long sS = (long)SEQ * SEQ;
    const long sF = (long)SEQ * DIM;
    const long sO = (long)SEQ * 2 * DIM;
    const __half* A = (z >> 3) ? (att + b * sS) : (at + b * sS);
    const __half* B = (z >> 3) ? (lpt + b * sF) : (vpt + b * sF);
    const long    co = b * sO + ((z >> 3) ? DIM : 0);
    gemm16_body<false, false, 4, 1, false>(
        A, nullptr, SEQ, B, nullptr, SEQ,
        nullptr, cb + co, nullptr, 2 * DIM, SEQ, nullptr, hsm);
}

__global__ __launch_bounds__(256, 2)
void out_gemm(const __half* __restrict__ cb,
              const __half* __restrict__ wo, const float* __restrict__ bo,
              float* __restrict__ out)
{
    extern __shared__ __half hsm[];
    gemm16_body<false, false, 3, 0, true>(
        cb, nullptr, 2 * DIM, wo, nullptr, 2 * DIM,
        out, nullptr, nullptr, DIM, 2 * DIM, bo, hsm);
}

// ---------------------------------------------------------------------------
// fp32 -> fp16 hi/lo split (elementwise), float4 granularity
// ---------------------------------------------------------------------------
__global__ __launch_bounds__(256)
void convert_split(const float* __restrict__ src, __half* __restrict__ h,
                   __half* __restrict__ l)
{
    const long i = (long)blockIdx.x * 256 + threadIdx.x;
    float4 v = reinterpret_cast<const float4*>(src)[i];
    __half hh[4], ll[4];
    split_h(v.x, hh[0], ll[0]); split_h(v.y, hh[1], ll[1]);
    split_h(v.z, hh[2], ll[2]); split_h(v.w, hh[3], ll[3]);
    uint2 ho, lo;
    *reinterpret_cast<__half2*>(&ho.x) = __halves2half2(hh[0], hh[1]);
    *reinterpret_cast<__half2*>(&ho.y) = __halves2half2(hh[2], hh[3]);
    *reinterpret_cast<__half2*>(&lo.x) = __halves2half2(ll[0], ll[1]);
    *reinterpret_cast<__half2*>(&lo.y) = __halves2half2(ll[2], ll[3]);
    reinterpret_cast<uint2*>(h)[i] = ho;
    reinterpret_cast<uint2*>(l)[i] = lo;
}

__global__ __launch_bounds__(256)
void wo_convert(const float* __restrict__ Wo, __half* __restrict__ wo16)
{
    const int i = blockIdx.x * 256 + threadIdx.x;
    float2 v = *reinterpret_cast<const float2*>(&Wo[i * 2]);
    *reinterpret_cast<__half2*>(&wo16[i * 2]) = __floats2half2_rn(v.x, v.y);
}

// ---------------------------------------------------------------------------
// fp16 tiled transposes
// ---------------------------------------------------------------------------
__global__ __launch_bounds__(256)
void transpose16(const __half* __restrict__ src, __half* __restrict__ dst,
                 int R, int C, long stride)
{
    __shared__ __half t[32][34];
    const long b  = blockIdx.z;
    const int  x0 = blockIdx.x * 32;
    const int  y0 = blockIdx.y * 32;
    const __half* s = src + b * stride;
    __half*       d = dst + b * stride;
    const int tx = threadIdx.x, ty = threadIdx.y;
#pragma unroll
    for (int i = 0; i < 4; ++i)
        t[ty + i * 8][tx] = s[(long)(y0 + ty + i * 8) * C + x0 + tx];
    __syncthreads();
#pragma unroll
    for (int i = 0; i < 4; ++i)
        d[(long)(x0 + ty + i * 8) * R + y0 + tx] = t[tx][ty + i * 8];
}

__global__ __launch_bounds__(256)
void transpose_vl(const __half* __restrict__ vph, __half* __restrict__ vpt,
                  const __half* __restrict__ lph, __half* __restrict__ lpt)
{
    __shared__ __half t[32][34];
    const int z = blockIdx.z;
    const long b  = z & 7;
    const long stride = (long)SEQ * DIM;
    const __half* s = ((z >> 3) ? lph : vph) + b * stride;
    __half*       d = ((z >> 3) ? lpt : vpt) + b * stride;
    const int x0 = blockIdx.x * 32;
    const int y0 = blockIdx.y * 32;
    const int tx = threadIdx.x & 31, ty = threadIdx.x >> 5;
#pragma unroll
    for (int i = 0; i < 4; ++i)
        t[ty + i * 8][tx] = s[(long)(y0 + ty + i * 8) * DIM + x0 + tx];
    __syncthreads();
#pragma unroll
    for (int i = 0; i < 4; ++i)
        d[(long)(x0 + ty + i * 8) * SEQ + y0 + tx] = t[tx][ty + i * 8];
}

// ---------------------------------------------------------------------------
// Row softmax: sim fp32 -> attn fp16. One block per row of 2048.
// ---------------------------------------------------------------------------
__global__ __launch_bounds__(256)
void softmax2048h(const float* __restrict__ S, __half* __restrict__ O)
{
    const float* p = S + (long)blockIdx.x * 2048;
    __half*      o = O + (long)blockIdx.x * 2048;
    const int tid = threadIdx.x;

    float4 v0 = reinterpret_cast<const float4*>(p)[tid];
    float4 v1 = reinterpret_cast<const float4*>(p)[tid + 256];

    float mx = fmaxf(fmaxf(fmaxf(v0.x, v0.y), fmaxf(v0.z, v0.w)),
                     fmaxf(fmaxf(v1.x, v1.y), fmaxf(v1.z, v1.w)));

    __shared__ float red[8];
#pragma unroll
    for (int ofs = 16; ofs > 0; ofs >>= 1) mx = fmaxf(mx, __shfl_xor_sync(0xffffffffu, mx, ofs));
    if ((tid & 31) == 0) red[tid >> 5] = mx;
    __syncthreads();
    if (tid == 0) {
        float m = red[0];
#pragma unroll
        for (int w = 1; w < 8; ++w) m = fmaxf(m, red[w]);
        red[0] = m;
    }
    __syncthreads();
    mx = red[0];
    __syncthreads();

    v0.x = __expf(v0.x - mx); v0.y = __expf(v0.y - mx);
    v0.z = __expf(v0.z - mx); v0.w = __expf(v0.w - mx);
    v1.x = __expf(v1.x - mx); v1.y = __expf(v1.y - mx);
    v1.z = __expf(v1.z - mx); v1.w = __expf(v1.w - mx);

    float s = (v0.x + v0.y + v0.z + v0.w) + (v1.x + v1.y + v1.z + v1.w);
#pragma unroll
    for (int ofs = 16; ofs > 0; ofs >>= 1) s += __shfl_xor_sync(0xffffffffu, s, ofs);
    if ((tid & 31) == 0) red[tid >> 5] = s;
    __syncthreads();
    if (tid == 0) {
        float t = 0.f;
#pragma unroll
        for (int w = 0; w < 8; ++w) t += red[w];
        red[0] = t;
    }
    __syncthreads();
    const float inv = 1.0f / red[0];

    uint2 o0, o1;
    *reinterpret_cast<__half2*>(&o0.x) = __floats2half2_rn(v0.x * inv, v0.y * inv);
    *reinterpret_cast<__half2*>(&o0.y) = __floats2half2_rn(v0.z * inv, v0.w * inv);
    *reinterpret_cast<__half2*>(&o1.x) = __floats2half2_rn(v1.x * inv, v1.y * inv);
    *reinterpret_cast<__half2*>(&o1.y) = __floats2half2_rn(v1.z * inv, v1.w * inv);
    reinterpret_cast<uint2*>(o)[tid]       = o0;
    reinterpret_cast<uint2*>(o)[tid + 256] = o1;
}

// ---------------------------------------------------------------------------
// Launch
// ---------------------------------------------------------------------------
extern "C" void kernel_launch(void* const* d_in, const int* in_sizes, int n_in,
                              void* d_out, int out_size)
{
    const float* Vf = (const float*)d_in[0];
    const float* Lf = (const float*)d_in[1];
    const float* Wv = (const float*)d_in[2];
    const float* bv = (const float*)d_in[3];
    const float* Wl = (const float*)d_in[4];
    const float* bl = (const float*)d_in[5];
    const float* Wo = (const float*)d_in[6];
    const float* bo = (const float*)d_in[7];
    float* out = (float*)d_out;

    __half *vfh, *vfl, *lfh, *lfl, *wvh, *wvl, *wlh, *wll;
    __half *vph, *vpl, *lph, *lpl, *vpt, *lpt, *at, *att, *cb, *wo16;
    float* sim;
    cudaGetSymbolAddress((void**)&vfh, g_vfh);
    cudaGetSymbolAddress((void**)&vfl, g_vfl);
    cudaGetSymbolAddress((void**)&lfh, g_lfh);
    cudaGetSymbolAddress((void**)&lfl, g_lfl);
    cudaGetSymbolAddress((void**)&wvh, g_wvh);
    cudaGetSymbolAddress((void**)&wvl, g_wvl);
    cudaGetSymbolAddress((void**)&wlh, g_wlh);
    cudaGetSymbolAddress((void**)&wll, g_wll);
    cudaGetSymbolAddress((void**)&vph, g_vph);
    cudaGetSymbolAddress((void**)&vpl, g_vpl);
    cudaGetSymbolAddress((void**)&lph, g_lph);
    cudaGetSymbolAddress((void**)&lpl, g_lpl);
    cudaGetSymbolAddress((void**)&vpt, g_vpt);
    cudaGetSymbolAddress((void**)&lpt, g_lpt);
    cudaGetSymbolAddress((void**)&sim, g_sim);
    cudaGetSymbolAddress((void**)&at,  g_at);
    cudaGetSymbolAddress((void**)&att, g_att);
    cudaGetSymbolAddress((void**)&cb,  g_cb);
    cudaGetSymbolAddress((void**)&wo16, g_wo16);

    const int S2 = 4 * TILE16 * 2 * 2;   // 81920 (proj, sim)
    const int S4 = 2 * TILE16 * 4 * 2;   // 81920 (avl)
    const int S3 = 2 * TILE16 * 3 * 2;   // 61440 (out)
    cudaFuncSetAttribute(proj_gemm, cudaFuncAttributeMaxDynamicSharedMemorySize, S2);
    cudaFuncSetAttribute(sim_gemm,  cudaFuncAttributeMaxDynamicSharedMemorySize, S2);
    cudaFuncSetAttribute(avl_gemm,  cudaFuncAttributeMaxDynamicSharedMemorySize, S4);
    cudaFuncSetAttribute(out_gemm,  cudaFuncAttributeMaxDynamicSharedMemorySize, S3);

    const dim3 blk(256);
    const long sS = (long)SEQ * SEQ;

    // input conversions
    wo_convert<<<DIM * 2 * DIM / 512, blk>>>(Wo, wo16);
    convert_split<<<TOK * DIM / 1024, blk>>>(Vf, vfh, vfl);
    convert_split<<<TOK * DIM / 1024, blk>>>(Lf, lfh, lfl);
    convert_split<<<DIM * DIM / 1024, blk>>>(Wv, wvh, wvl);
    convert_split<<<DIM * DIM / 1024, blk>>>(Wl, wlh, wll);
    // projections (3x) -> vp/lp hi+lo fp16
    proj_gemm<<<dim3(DIM/128, TOK/128, 2), blk, S2>>>(
        vfh, vfl, lfh, lfl, wvh, wvl, wlh, wll, bv, bl, vph, vpl, lph, lpl);
    // vp^T and lp^T, one launch
    transpose_vl<<<dim3(DIM/32, SEQ/32, 2 * BATCH), blk>>>(vph, vpt, lph, lpt);
    // sim (3x)
    sim_gemm<<<dim3(SEQ/128, SEQ/128, BATCH), blk, S2>>>(vph, vpl, lph, lpl, sim);
    // softmax -> attn fp16
    softmax2048h<<<TOK, blk>>>(sim, at);
    // attn^T fp16
    transpose16<<<dim3(SEQ/32, SEQ/32, BATCH), dim3(32, 8)>>>(at, att, SEQ, SEQ, sS);
    // av + al (1x) -> comb fp16
    avl_gemm<<<dim3(DIM/128, SEQ/128, 2 * BATCH), blk, S4>>>(at, att, vpt, lpt, cb);
    // out (1x)
    out_gemm<<<dim3(DIM/128, TOK/128, 1), blk, S3>>>(cb, wo16, bo, out);
}